// round 11
// baseline (speedup 1.0000x reference)
#include <cuda_runtime.h>
#include <cuda_bf16.h>
#include <cstdint>
#include <math.h>

#define Bsz  4
#define Cdim 256
#define Ddim 128
#define Nn   4096

// Scratch (static __device__ — no allocations allowed)
__device__ __nv_bfloat16 g_Qh[Bsz * Nn * Ddim];
__device__ __nv_bfloat16 g_Ql[Bsz * Nn * Ddim];
__device__ __nv_bfloat16 g_Kh[Bsz * Nn * Ddim];
__device__ __nv_bfloat16 g_Kl[Bsz * Nn * Ddim];
__device__ float g_V[Bsz * Nn * Ddim];                 // tf32-pre-rounded
__device__ __nv_bfloat16 g_Yh[Bsz * Nn * Ddim];
__device__ __nv_bfloat16 g_Yl[Bsz * Nn * Ddim];
__device__ __nv_bfloat16 g_Xth[Bsz * Nn * Cdim];       // x^T split
__device__ __nv_bfloat16 g_Xtl[Bsz * Nn * Cdim];
__device__ __nv_bfloat16 g_Wh[4 * 32768];              // wt,wp,wg,w_out split
__device__ __nv_bfloat16 g_Wl[4 * 32768];

__device__ __forceinline__ uint32_t f2tf(float x) {
    uint32_t r;
    asm("cvt.rna.tf32.f32 %0, %1;" : "=r"(r) : "f"(x));
    return r;
}

__device__ __forceinline__ void mma8(float* c, const uint32_t* a, const uint32_t* b) {
    asm volatile(
        "mma.sync.aligned.m16n8k8.row.col.f32.tf32.tf32.f32 "
        "{%0,%1,%2,%3},{%4,%5,%6,%7},{%8,%9},{%0,%1,%2,%3};"
        : "+f"(c[0]), "+f"(c[1]), "+f"(c[2]), "+f"(c[3])
        : "r"(a[0]), "r"(a[1]), "r"(a[2]), "r"(a[3]), "r"(b[0]), "r"(b[1]));
}

__device__ __forceinline__ void mma16(float* c, const uint32_t* a, const uint32_t* b) {
    asm volatile(
        "mma.sync.aligned.m16n8k16.row.col.f32.bf16.bf16.f32 "
        "{%0,%1,%2,%3},{%4,%5,%6,%7},{%8,%9},{%0,%1,%2,%3};"
        : "+f"(c[0]), "+f"(c[1]), "+f"(c[2]), "+f"(c[3])
        : "r"(a[0]), "r"(a[1]), "r"(a[2]), "r"(a[3]), "r"(b[0]), "r"(b[1]));
}

__device__ __forceinline__ void ldsm4(uint32_t* r, uint32_t addr) {
    asm volatile(
        "ldmatrix.sync.aligned.m8n8.x4.shared.b16 {%0,%1,%2,%3}, [%4];"
        : "=r"(r[0]), "=r"(r[1]), "=r"(r[2]), "=r"(r[3]) : "r"(addr));
}

__device__ __forceinline__ uint32_t smem_u32(const void* p) {
    uint32_t a;
    asm("{ .reg .u64 t; cvta.to.shared.u64 t, %1; cvt.u32.u64 %0, t; }" : "=r"(a) : "l"(p));
    return a;
}

// ---------------------------------------------------------------------------
// Prep 1: split all 4 fp32 weights into bf16 hi/lo (one launch).
// ---------------------------------------------------------------------------
__global__ void split_w4_kernel(const float* __restrict__ w0, const float* __restrict__ w1,
                                const float* __restrict__ w2, const float* __restrict__ w3) {
    int slot = blockIdx.y;
    const float* src = (slot == 0) ? w0 : (slot == 1) ? w1 : (slot == 2) ? w2 : w3;
    int i = blockIdx.x * 256 + threadIdx.x;
    float v = src[i];
    __nv_bfloat16 h = __float2bfloat16_rn(v);
    __nv_bfloat16 l = __float2bfloat16_rn(v - __bfloat162float(h));
    g_Wh[slot * 32768 + i] = h;
    g_Wl[slot * 32768 + i] = l;
}

// ---------------------------------------------------------------------------
// Prep 2: transpose-split x[b][c][n] -> xt[b][n][c] bf16 hi/lo.
// ---------------------------------------------------------------------------
__global__ void xpose_kernel(const float* __restrict__ x) {
    __shared__ float tsm[32][33];
    const int b = blockIdx.z, n0 = blockIdx.x * 32, c0 = blockIdx.y * 32;
    const int tx = threadIdx.x & 31, ty = threadIdx.x >> 5;
    const float* xb = x + (size_t)b * Cdim * Nn;
    #pragma unroll
    for (int i = 0; i < 4; i++)
        tsm[ty + 8 * i][tx] = xb[(size_t)(c0 + ty + 8 * i) * Nn + n0 + tx];
    __syncthreads();
    #pragma unroll
    for (int i = 0; i < 4; i++) {
        float v = tsm[tx][ty + 8 * i];
        __nv_bfloat16 h = __float2bfloat16_rn(v);
        __nv_bfloat16 l = __float2bfloat16_rn(v - __bfloat162float(h));
        size_t o = ((size_t)b * Nn + n0 + ty + 8 * i) * Cdim + c0 + tx;
        g_Xth[o] = h;
        g_Xtl[o] = l;
    }
}

// ---------------------------------------------------------------------------
// Kernel 1: QKV projection on tensor cores (unchanged from R8 pass).
// ---------------------------------------------------------------------------
#define P36 36
#define QKV_XH 0
#define QKV_XL (128 * P36)
#define QKV_WH (2 * 128 * P36)
#define QKV_WL (3 * 128 * P36)
#define QKV_SMEM (4 * 128 * P36 * 4)

__global__ void __launch_bounds__(256, 1) qkv_tc_kernel() {
    extern __shared__ uint32_t S[];
    const int b = blockIdx.z, slot = blockIdx.y, n0 = blockIdx.x * 128;
    const int tid = threadIdx.x;
    const int lane = tid & 31, w = tid >> 5;
    const int g = lane >> 2, t = lane & 3;
    const int row0 = w * 16 + g, row1 = row0 + 8;

    const uint32_t* Xhw = (const uint32_t*)g_Xth;
    const uint32_t* Xlw = (const uint32_t*)g_Xtl;
    const uint32_t* Whw = (const uint32_t*)(g_Wh + slot * 32768);
    const uint32_t* Wlw = (const uint32_t*)(g_Wl + slot * 32768);

    float acc[16][4];
    #pragma unroll
    for (int nb = 0; nb < 16; nb++)
        #pragma unroll
        for (int c = 0; c < 4; c++) acc[nb][c] = 0.f;

    for (int chunk = 0; chunk < 4; chunk++) {
        const int c0 = chunk * 64;
        __syncthreads();
        #pragma unroll
        for (int i = 0; i < 4; i++) {
            int f = tid + i * 256;
            int r = f >> 3, w4 = (f & 7) * 4;
            size_t xb = ((size_t)(b * Nn + n0 + r) * Cdim + c0) >> 1;
            *(uint4*)&S[QKV_XH + r * P36 + w4] = *(const uint4*)&Xhw[xb + w4];
            *(uint4*)&S[QKV_XL + r * P36 + w4] = *(const uint4*)&Xlw[xb + w4];
            int wb = r * 128 + (c0 >> 1);
            *(uint4*)&S[QKV_WH + r * P36 + w4] = *(const uint4*)&Whw[wb + w4];
            *(uint4*)&S[QKV_WL + r * P36 + w4] = *(const uint4*)&Wlw[wb + w4];
        }
        __syncthreads();

        #pragma unroll
        for (int kb = 0; kb < 4; kb++) {
            const int kw = kb * 8 + t;
            uint32_t ah[4], al[4];
            ah[0] = S[QKV_XH + row0 * P36 + kw];
            ah[1] = S[QKV_XH + row1 * P36 + kw];
            ah[2] = S[QKV_XH + row0 * P36 + kw + 4];
            ah[3] = S[QKV_XH + row1 * P36 + kw + 4];
            al[0] = S[QKV_XL + row0 * P36 + kw];
            al[1] = S[QKV_XL + row1 * P36 + kw];
            al[2] = S[QKV_XL + row0 * P36 + kw + 4];
            al[3] = S[QKV_XL + row1 * P36 + kw + 4];
            #pragma unroll
            for (int nb = 0; nb < 16; nb++) {
                const int rr = nb * 8 + g;
                uint32_t bh[2], bl[2];
                bh[0] = S[QKV_WH + rr * P36 + kw];
                bh[1] = S[QKV_WH + rr * P36 + kw + 4];
                bl[0] = S[QKV_WL + rr * P36 + kw];
                bl[1] = S[QKV_WL + rr * P36 + kw + 4];
                mma16(acc[nb], ah, bh);
                mma16(acc[nb], ah, bl);
                mma16(acc[nb], al, bh);
            }
        }
    }

    const size_t base0 = ((size_t)b * Nn + n0 + row0) * Ddim;
    const size_t base1 = ((size_t)b * Nn + n0 + row1) * Ddim;
    if (slot == 2) {
        #pragma unroll
        for (int nb = 0; nb < 16; nb++) {
            const int d = nb * 8 + t * 2;
            *(float2*)&g_V[base0 + d] = make_float2(
                __uint_as_float(f2tf(acc[nb][0])), __uint_as_float(f2tf(acc[nb][1])));
            *(float2*)&g_V[base1 + d] = make_float2(
                __uint_as_float(f2tf(acc[nb][2])), __uint_as_float(f2tf(acc[nb][3])));
        }
    } else {
        __nv_bfloat16* Hh = (slot == 0) ? g_Qh : g_Kh;
        __nv_bfloat16* Hl = (slot == 0) ? g_Ql : g_Kl;
        #pragma unroll
        for (int nb = 0; nb < 16; nb++) {
            const int d = nb * 8 + t * 2;
            __nv_bfloat162 h0, l0, h1, l1;
            h0.x = __float2bfloat16_rn(acc[nb][0]);
            h0.y = __float2bfloat16_rn(acc[nb][1]);
            l0.x = __float2bfloat16_rn(acc[nb][0] - __bfloat162float(h0.x));
            l0.y = __float2bfloat16_rn(acc[nb][1] - __bfloat162float(h0.y));
            h1.x = __float2bfloat16_rn(acc[nb][2]);
            h1.y = __float2bfloat16_rn(acc[nb][3]);
            l1.x = __float2bfloat16_rn(acc[nb][2] - __bfloat162float(h1.x));
            l1.y = __float2bfloat16_rn(acc[nb][3] - __bfloat162float(h1.y));
            *(__nv_bfloat162*)&Hh[base0 + d] = h0;
            *(__nv_bfloat162*)&Hl[base0 + d] = l0;
            *(__nv_bfloat162*)&Hh[base1 + d] = h1;
            *(__nv_bfloat162*)&Hl[base1 + d] = l1;
        }
    }
}

// ---------------------------------------------------------------------------
// Kernel 2: flash attention, q-tile 64, 128 threads (4 warps), 2 CTAs/SM.
// Each warp = one R10-style warp (16 rows, full K-tile 64, full d 128).
// P buffer ALIASES the Kl buffer (Kl dead after S-phase; barrier separates).
// No-max softmax (validated R10): no cross-warp coordination in mainloop.
// SMEM = 104.4 KB -> 2 independent CTAs per SM hide each other's latency.
// ---------------------------------------------------------------------------
#define QW 68
#define VW 136
#define PW 68
#define A_QH 0
#define A_QL (64 * QW)
#define A_KH (2 * 64 * QW)
#define A_KLP (3 * 64 * QW)                 // Kl during S; P afterwards
#define A_VS (4 * 64 * QW)
#define ATTN_WORDS (A_VS + 64 * VW)
#define ATTN_SMEM (ATTN_WORDS * 4)

__global__ void __launch_bounds__(128, 2) attn_kernel() {
    extern __shared__ float sm[];
    uint32_t* Qh = (uint32_t*)sm + A_QH;
    uint32_t* Ql = (uint32_t*)sm + A_QL;
    uint32_t* Kh = (uint32_t*)sm + A_KH;
    uint32_t* Kl = (uint32_t*)sm + A_KLP;
    float*    Ps = sm + A_KLP;              // alias of Kl
    float*    Vs = sm + A_VS;

    const uint32_t sb  = smem_u32(sm);
    const uint32_t bQH = sb + A_QH * 4;
    const uint32_t bQL = sb + A_QL * 4;
    const uint32_t bKH = sb + A_KH * 4;
    const uint32_t bKL = sb + A_KLP * 4;

    const int b  = blockIdx.y;
    const int q0 = blockIdx.x * 64;
    const uint32_t* Qgh = (const uint32_t*)(g_Qh + ((size_t)b * Nn + q0) * Ddim);
    const uint32_t* Qgl = (const uint32_t*)(g_Ql + ((size_t)b * Nn + q0) * Ddim);
    const uint32_t* Kgh = (const uint32_t*)(g_Kh + (size_t)b * Nn * Ddim);
    const uint32_t* Kgl = (const uint32_t*)(g_Kl + (size_t)b * Nn * Ddim);
    const float*    Vg  = g_V + (size_t)b * Nn * Ddim;

    const int tid  = threadIdx.x;
    const int lane = tid & 31;
    const int w    = tid >> 5;               // 0..3
    const int g    = lane >> 2;
    const int t    = lane & 3;
    const int row0 = w * 16 + g;
    const int row1 = row0 + 8;

    // ldmatrix per-thread address offsets (bytes)
    const uint32_t aOff = ((uint32_t)(w * 16 + (lane & 7) + ((lane >> 3) & 1) * 8) * QW
                          + (lane >> 4) * 4) * 4;
    const uint32_t bOff = ((uint32_t)((lane >> 4) * 8 + (lane & 7)) * QW
                          + ((lane >> 3) & 1) * 4) * 4;

    // Load Q tile (64 rows x 64 words, hi+lo): 1024 uint4 each, 128 thr -> 8 iters
    #pragma unroll
    for (int i = 0; i < 8; i++) {
        int f = tid + i * 128;
        int r = f >> 4, cw = (f & 15) * 4;
        *(uint4*)&Qh[r * QW + cw] = *(const uint4*)&Qgh[r * 64 + cw];
        *(uint4*)&Ql[r * QW + cw] = *(const uint4*)&Qgl[r * 64 + cw];
    }

    float l0 = 0.f, l1 = 0.f;
    float o[16][4];
    #pragma unroll
    for (int nb = 0; nb < 16; nb++)
        #pragma unroll
        for (int c = 0; c < 4; c++) o[nb][c] = 0.f;

    for (int j0 = 0; j0 < Nn; j0 += 64) {
        __syncthreads();   // prior PV reads of Ps/Vs done; safe to restage K/V
        // Stage K hi/lo (1024 uint4 each) and V (2048 float4)
        #pragma unroll
        for (int i = 0; i < 8; i++) {
            int f = tid + i * 128;
            int r = f >> 4, cw = (f & 15) * 4;
            *(uint4*)&Kh[r * QW + cw] = *(const uint4*)&Kgh[(size_t)(j0 + r) * 64 + cw];
            *(uint4*)&Kl[r * QW + cw] = *(const uint4*)&Kgl[(size_t)(j0 + r) * 64 + cw];
        }
        #pragma unroll
        for (int i = 0; i < 16; i++) {
            int f = tid + i * 128;
            int r = f >> 5, c4 = (f & 31) * 4;
            *(float4*)&Vs[r * VW + c4] = *(const float4*)&Vg[(size_t)(j0 + r) * Ddim + c4];
        }
        __syncthreads();

        // ---- S = Q K^T via ldmatrix fragments (bf16 3-split) ----
        float s[8][4];
        #pragma unroll
        for (int nb = 0; nb < 8; nb++)
            #pragma unroll
            for (int c = 0; c < 4; c++) s[nb][c] = 0.f;

        #pragma unroll
        for (int kb = 0; kb < 8; kb++) {
            const uint32_t kByte = kb * 32;
            uint32_t ah[4], al[4];
            ldsm4(ah, bQH + aOff + kByte);
            ldsm4(al, bQL + aOff + kByte);
            #pragma unroll
            for (int nbp = 0; nbp < 4; nbp++) {
                const uint32_t bo = bOff + (uint32_t)nbp * 16 * QW * 4 + kByte;
                uint32_t bh[4], bl[4];
                ldsm4(bh, bKH + bo);
                ldsm4(bl, bKL + bo);
                mma16(s[2 * nbp],     ah, &bh[0]);
                mma16(s[2 * nbp],     ah, &bl[0]);
                mma16(s[2 * nbp],     al, &bh[0]);
                mma16(s[2 * nbp + 1], ah, &bh[2]);
                mma16(s[2 * nbp + 1], ah, &bl[2]);
                mma16(s[2 * nbp + 1], al, &bh[2]);
            }
        }
        __syncthreads();   // all warps done reading Kl -> region reusable as P

        // ---- softmax without max subtraction: p = exp(s); write P over Kl ----
        #pragma unroll
        for (int nb = 0; nb < 8; nb++) {
            float p0 = __expf(s[nb][0]);
            float p1 = __expf(s[nb][1]);
            float p2 = __expf(s[nb][2]);
            float p3 = __expf(s[nb][3]);
            l0 += p0 + p1;
            l1 += p2 + p3;
            float2 hi = make_float2(__uint_as_float(f2tf(p0)), __uint_as_float(f2tf(p1)));
            float2 lo = make_float2(__uint_as_float(f2tf(p2)), __uint_as_float(f2tf(p3)));
            *(float2*)&Ps[row0 * PW + nb * 8 + t * 2] = hi;
            *(float2*)&Ps[row1 * PW + nb * 8 + t * 2] = lo;
        }
        __syncthreads();   // P ready for all warps

        // ---- O += P V (tf32) ----
        #pragma unroll
        for (int kb = 0; kb < 8; kb++) {
            const int kc = kb * 8 + t;
            uint32_t pa[4];
            pa[0] = __float_as_uint(Ps[row0 * PW + kc]);
            pa[1] = __float_as_uint(Ps[row1 * PW + kc]);
            pa[2] = __float_as_uint(Ps[row0 * PW + kc + 4]);
            pa[3] = __float_as_uint(Ps[row1 * PW + kc + 4]);
            #pragma unroll
            for (int nb = 0; nb < 16; nb++) {
                uint32_t vb[2];
                vb[0] = __float_as_uint(Vs[(kb * 8 + t) * VW + nb * 8 + g]);
                vb[1] = __float_as_uint(Vs[(kb * 8 + t + 4) * VW + nb * 8 + g]);
                mma8(o[nb], pa, vb);
            }
        }
    }

    // ---- epilogue: reduce l across 4 lanes of the row, normalize, write ----
    l0 += __shfl_xor_sync(0xffffffffu, l0, 1);
    l0 += __shfl_xor_sync(0xffffffffu, l0, 2);
    l1 += __shfl_xor_sync(0xffffffffu, l1, 1);
    l1 += __shfl_xor_sync(0xffffffffu, l1, 2);
    float inv0 = 1.f / l0, inv1 = 1.f / l1;
    const size_t base0 = ((size_t)b * Nn + q0 + row0) * Ddim;
    const size_t base1 = ((size_t)b * Nn + q0 + row1) * Ddim;
    #pragma unroll
    for (int nb = 0; nb < 16; nb++) {
        const int d = nb * 8 + t * 2;
        float y00 = o[nb][0] * inv0, y01 = o[nb][1] * inv0;
        float y10 = o[nb][2] * inv1, y11 = o[nb][3] * inv1;
        __nv_bfloat162 h0, l0v, h1, l1v;
        h0.x = __float2bfloat16_rn(y00);
        h0.y = __float2bfloat16_rn(y01);
        l0v.x = __float2bfloat16_rn(y00 - __bfloat162float(h0.x));
        l0v.y = __float2bfloat16_rn(y01 - __bfloat162float(h0.y));
        h1.x = __float2bfloat16_rn(y10);
        h1.y = __float2bfloat16_rn(y11);
        l1v.x = __float2bfloat16_rn(y10 - __bfloat162float(h1.x));
        l1v.y = __float2bfloat16_rn(y11 - __bfloat162float(h1.y));
        *(__nv_bfloat162*)&g_Yh[base0 + d] = h0;
        *(__nv_bfloat162*)&g_Yl[base0 + d] = l0v;
        *(__nv_bfloat162*)&g_Yh[base1 + d] = h1;
        *(__nv_bfloat162*)&g_Yl[base1 + d] = l1v;
    }
}

// ---------------------------------------------------------------------------
// Kernel 3: out = x + w_out * y on tensor cores (unchanged from R8 pass).
// ---------------------------------------------------------------------------
#define OUT_AH 0
#define OUT_AL (128 * P36)
#define OUT_BH (2 * 128 * P36)
#define OUT_BL (2 * 128 * P36 + 64 * P36)
#define OUT_SMEM ((2 * 128 * P36 + 2 * 64 * P36) * 4)

__global__ void __launch_bounds__(256) out_tc_kernel(const float* __restrict__ x,
                                                     float* __restrict__ out) {
    extern __shared__ uint32_t S[];
    const int b = blockIdx.z, c0 = blockIdx.y * 128, n0 = blockIdx.x * 64;
    const int tid = threadIdx.x;
    const int lane = tid & 31, w = tid >> 5;
    const int g = lane >> 2, t = lane & 3;
    const int row0 = w * 16 + g, row1 = row0 + 8;

    const uint32_t* Ahw = (const uint32_t*)(g_Wh + 3 * 32768);
    const uint32_t* Alw = (const uint32_t*)(g_Wl + 3 * 32768);
    const uint32_t* Bhw = (const uint32_t*)g_Yh;
    const uint32_t* Blw = (const uint32_t*)g_Yl;

    float acc[8][4];
    #pragma unroll
    for (int nb = 0; nb < 8; nb++)
        #pragma unroll
        for (int c = 0; c < 4; c++) acc[nb][c] = 0.f;

    for (int chunk = 0; chunk < 2; chunk++) {
        const int dd0 = chunk * 64;
        __syncthreads();
        #pragma unroll
        for (int i = 0; i < 4; i++) {
            int f = tid + i * 256;
            int r = f >> 3, w4 = (f & 7) * 4;
            int ab = (c0 + r) * 64 + (dd0 >> 1);
            *(uint4*)&S[OUT_AH + r * P36 + w4] = *(const uint4*)&Ahw[ab + w4];
            *(uint4*)&S[OUT_AL + r * P36 + w4] = *(const uint4*)&Alw[ab + w4];
        }
        #pragma unroll
        for (int i = 0; i < 2; i++) {
            int f = tid + i * 256;
            int r = f >> 3, w4 = (f & 7) * 4;
            size_t bb = ((size_t)(b * Nn + n0 + r) * Ddim + dd0) >> 1;
            *(uint4*)&S[OUT_BH + r * P36 + w4] = *(const uint4*)&Bhw[bb + w4];
            *(uint4*)&S[OUT_BL + r * P36 + w4] = *(const uint4*)&Blw[bb + w4];
        }
        __syncthreads();

        #pragma unroll
        for (int kb = 0; kb < 4; kb++) {
            const int kw = kb * 8 + t;
            uint32_t ah[4], al[4];
            ah[0] = S[OUT_AH + row0 * P36 + kw];
            ah[1] = S[OUT_AH + row1 * P36 + kw];
            ah[2] = S[OUT_AH + row0 * P36 + kw + 4];
            ah[3] = S[OUT_AH + row1 * P36 + kw + 4];
            al[0] = S[OUT_AL + row0 * P36 + kw];
            al[1] = S[OUT_AL + row1 * P36 + kw];
            al[2] = S[OUT_AL + row0 * P36 + kw + 4];
            al[3] = S[OUT_AL + row1 * P36 + kw + 4];
            #pragma unroll
            for (int nb = 0; nb < 8; nb++) {
                const int rr = nb * 8 + g;
                uint32_t bh[2], bl[2];
                bh[0] = S[OUT_BH + rr * P36 + kw];
                bh[1] = S[OUT_BH + rr * P36 + kw + 4];
                bl[0] = S[OUT_BL + rr * P36 + kw];
                bl[1] = S[OUT_BL + rr * P36 + kw + 4];
                mma16(acc[nb], ah, bh);
                mma16(acc[nb], ah, bl);
                mma16(acc[nb], al, bh);
            }
        }
    }

    const int ch0 = c0 + row0, ch1 = c0 + row1;
    #pragma unroll
    for (int nb = 0; nb < 8; nb++) {
        const int pix = n0 + nb * 8 + t * 2;
        size_t i0 = (size_t)b * Cdim * Nn + (size_t)ch0 * Nn + pix;
        size_t i1 = (size_t)b * Cdim * Nn + (size_t)ch1 * Nn + pix;
        float2 x0 = *(const float2*)&x[i0];
        float2 x1 = *(const float2*)&x[i1];
        *(float2*)&out[i0] = make_float2(x0.x + acc[nb][0], x0.y + acc[nb][1]);
        *(float2*)&out[i1] = make_float2(x1.x + acc[nb][2], x1.y + acc[nb][3]);
    }
}

// ---------------------------------------------------------------------------
extern "C" void kernel_launch(void* const* d_in, const int* in_sizes, int n_in,
                              void* d_out, int out_size) {
    const float* x  = (const float*)d_in[0];
    const float* wt = (const float*)d_in[1];
    const float* wp = (const float*)d_in[2];
    const float* wg = (const float*)d_in[3];
    const float* wo = (const float*)d_in[4];
    float* out = (float*)d_out;

    cudaFuncSetAttribute(attn_kernel,
                         cudaFuncAttributeMaxDynamicSharedMemorySize, ATTN_SMEM);
    cudaFuncSetAttribute(qkv_tc_kernel,
                         cudaFuncAttributeMaxDynamicSharedMemorySize, QKV_SMEM);
    cudaFuncSetAttribute(out_tc_kernel,
                         cudaFuncAttributeMaxDynamicSharedMemorySize, OUT_SMEM);

    split_w4_kernel<<<dim3(128, 4), 256>>>(wt, wp, wg, wo);
    xpose_kernel<<<dim3(Nn / 32, Cdim / 32, Bsz), 256>>>(x);
    qkv_tc_kernel<<<dim3(Nn / 128, 3, Bsz), 256, QKV_SMEM>>>();
    attn_kernel<<<dim3(Nn / 64, Bsz), 128, ATTN_SMEM>>>();
    out_tc_kernel<<<dim3(Nn / 64, Cdim / 128, Bsz), 256, OUT_SMEM>>>(x, out);
}

// round 12
// speedup vs baseline: 1.3131x; 1.3131x over previous
#include <cuda_runtime.h>
#include <cuda_bf16.h>
#include <cuda_fp16.h>
#include <cstdint>
#include <math.h>

#define Bsz  4
#define Cdim 256
#define Ddim 128
#define Nn   4096

// Scratch (static __device__ — no allocations allowed)
__device__ __nv_bfloat16 g_Qh[Bsz * Nn * Ddim];
__device__ __nv_bfloat16 g_Ql[Bsz * Nn * Ddim];
__device__ __nv_bfloat16 g_Kh[Bsz * Nn * Ddim];
__device__ __nv_bfloat16 g_Kl[Bsz * Nn * Ddim];
__device__ __half g_V[Bsz * Nn * Ddim];                // fp16 V
__device__ __nv_bfloat16 g_Yh[Bsz * Nn * Ddim];
__device__ __nv_bfloat16 g_Yl[Bsz * Nn * Ddim];
__device__ __nv_bfloat16 g_Xth[Bsz * Nn * Cdim];       // x^T split
__device__ __nv_bfloat16 g_Xtl[Bsz * Nn * Cdim];
__device__ __nv_bfloat16 g_Wh[4 * 32768];              // wt,wp,wg,w_out split
__device__ __nv_bfloat16 g_Wl[4 * 32768];

__device__ __forceinline__ void mma16(float* c, const uint32_t* a, const uint32_t* b) {
    asm volatile(
        "mma.sync.aligned.m16n8k16.row.col.f32.bf16.bf16.f32 "
        "{%0,%1,%2,%3},{%4,%5,%6,%7},{%8,%9},{%0,%1,%2,%3};"
        : "+f"(c[0]), "+f"(c[1]), "+f"(c[2]), "+f"(c[3])
        : "r"(a[0]), "r"(a[1]), "r"(a[2]), "r"(a[3]), "r"(b[0]), "r"(b[1]));
}

__device__ __forceinline__ void mma16h(float* c, const uint32_t* a, const uint32_t* b) {
    asm volatile(
        "mma.sync.aligned.m16n8k16.row.col.f32.f16.f16.f32 "
        "{%0,%1,%2,%3},{%4,%5,%6,%7},{%8,%9},{%0,%1,%2,%3};"
        : "+f"(c[0]), "+f"(c[1]), "+f"(c[2]), "+f"(c[3])
        : "r"(a[0]), "r"(a[1]), "r"(a[2]), "r"(a[3]), "r"(b[0]), "r"(b[1]));
}

__device__ __forceinline__ void ldsm4(uint32_t* r, uint32_t addr) {
    asm volatile(
        "ldmatrix.sync.aligned.m8n8.x4.shared.b16 {%0,%1,%2,%3}, [%4];"
        : "=r"(r[0]), "=r"(r[1]), "=r"(r[2]), "=r"(r[3]) : "r"(addr));
}

__device__ __forceinline__ void ldsm4t(uint32_t* r, uint32_t addr) {
    asm volatile(
        "ldmatrix.sync.aligned.m8n8.x4.trans.shared.b16 {%0,%1,%2,%3}, [%4];"
        : "=r"(r[0]), "=r"(r[1]), "=r"(r[2]), "=r"(r[3]) : "r"(addr));
}

__device__ __forceinline__ uint32_t smem_u32(const void* p) {
    uint32_t a;
    asm("{ .reg .u64 t; cvta.to.shared.u64 t, %1; cvt.u32.u64 %0, t; }" : "=r"(a) : "l"(p));
    return a;
}

// ---------------------------------------------------------------------------
// Prep 1: split all 4 fp32 weights into bf16 hi/lo (one launch).
// ---------------------------------------------------------------------------
__global__ void split_w4_kernel(const float* __restrict__ w0, const float* __restrict__ w1,
                                const float* __restrict__ w2, const float* __restrict__ w3) {
    int slot = blockIdx.y;
    const float* src = (slot == 0) ? w0 : (slot == 1) ? w1 : (slot == 2) ? w2 : w3;
    int i = blockIdx.x * 256 + threadIdx.x;
    float v = src[i];
    __nv_bfloat16 h = __float2bfloat16_rn(v);
    __nv_bfloat16 l = __float2bfloat16_rn(v - __bfloat162float(h));
    g_Wh[slot * 32768 + i] = h;
    g_Wl[slot * 32768 + i] = l;
}

// ---------------------------------------------------------------------------
// Prep 2: transpose-split x[b][c][n] -> xt[b][n][c] bf16 hi/lo.
// ---------------------------------------------------------------------------
__global__ void xpose_kernel(const float* __restrict__ x) {
    __shared__ float tsm[32][33];
    const int b = blockIdx.z, n0 = blockIdx.x * 32, c0 = blockIdx.y * 32;
    const int tx = threadIdx.x & 31, ty = threadIdx.x >> 5;
    const float* xb = x + (size_t)b * Cdim * Nn;
    #pragma unroll
    for (int i = 0; i < 4; i++)
        tsm[ty + 8 * i][tx] = xb[(size_t)(c0 + ty + 8 * i) * Nn + n0 + tx];
    __syncthreads();
    #pragma unroll
    for (int i = 0; i < 4; i++) {
        float v = tsm[tx][ty + 8 * i];
        __nv_bfloat16 h = __float2bfloat16_rn(v);
        __nv_bfloat16 l = __float2bfloat16_rn(v - __bfloat162float(h));
        size_t o = ((size_t)b * Nn + n0 + ty + 8 * i) * Cdim + c0 + tx;
        g_Xth[o] = h;
        g_Xtl[o] = l;
    }
}

// ---------------------------------------------------------------------------
// Kernel 1: QKV projection on tensor cores. Slot 2 (V) now writes fp16.
// ---------------------------------------------------------------------------
#define P36 36
#define QKV_XH 0
#define QKV_XL (128 * P36)
#define QKV_WH (2 * 128 * P36)
#define QKV_WL (3 * 128 * P36)
#define QKV_SMEM (4 * 128 * P36 * 4)

__global__ void __launch_bounds__(256, 1) qkv_tc_kernel() {
    extern __shared__ uint32_t S[];
    const int b = blockIdx.z, slot = blockIdx.y, n0 = blockIdx.x * 128;
    const int tid = threadIdx.x;
    const int lane = tid & 31, w = tid >> 5;
    const int g = lane >> 2, t = lane & 3;
    const int row0 = w * 16 + g, row1 = row0 + 8;

    const uint32_t* Xhw = (const uint32_t*)g_Xth;
    const uint32_t* Xlw = (const uint32_t*)g_Xtl;
    const uint32_t* Whw = (const uint32_t*)(g_Wh + slot * 32768);
    const uint32_t* Wlw = (const uint32_t*)(g_Wl + slot * 32768);

    float acc[16][4];
    #pragma unroll
    for (int nb = 0; nb < 16; nb++)
        #pragma unroll
        for (int c = 0; c < 4; c++) acc[nb][c] = 0.f;

    for (int chunk = 0; chunk < 4; chunk++) {
        const int c0 = chunk * 64;
        __syncthreads();
        #pragma unroll
        for (int i = 0; i < 4; i++) {
            int f = tid + i * 256;
            int r = f >> 3, w4 = (f & 7) * 4;
            size_t xb = ((size_t)(b * Nn + n0 + r) * Cdim + c0) >> 1;
            *(uint4*)&S[QKV_XH + r * P36 + w4] = *(const uint4*)&Xhw[xb + w4];
            *(uint4*)&S[QKV_XL + r * P36 + w4] = *(const uint4*)&Xlw[xb + w4];
            int wb = r * 128 + (c0 >> 1);
            *(uint4*)&S[QKV_WH + r * P36 + w4] = *(const uint4*)&Whw[wb + w4];
            *(uint4*)&S[QKV_WL + r * P36 + w4] = *(const uint4*)&Wlw[wb + w4];
        }
        __syncthreads();

        #pragma unroll
        for (int kb = 0; kb < 4; kb++) {
            const int kw = kb * 8 + t;
            uint32_t ah[4], al[4];
            ah[0] = S[QKV_XH + row0 * P36 + kw];
            ah[1] = S[QKV_XH + row1 * P36 + kw];
            ah[2] = S[QKV_XH + row0 * P36 + kw + 4];
            ah[3] = S[QKV_XH + row1 * P36 + kw + 4];
            al[0] = S[QKV_XL + row0 * P36 + kw];
            al[1] = S[QKV_XL + row1 * P36 + kw];
            al[2] = S[QKV_XL + row0 * P36 + kw + 4];
            al[3] = S[QKV_XL + row1 * P36 + kw + 4];
            #pragma unroll
            for (int nb = 0; nb < 16; nb++) {
                const int rr = nb * 8 + g;
                uint32_t bh[2], bl[2];
                bh[0] = S[QKV_WH + rr * P36 + kw];
                bh[1] = S[QKV_WH + rr * P36 + kw + 4];
                bl[0] = S[QKV_WL + rr * P36 + kw];
                bl[1] = S[QKV_WL + rr * P36 + kw + 4];
                mma16(acc[nb], ah, bh);
                mma16(acc[nb], ah, bl);
                mma16(acc[nb], al, bh);
            }
        }
    }

    const size_t base0 = ((size_t)b * Nn + n0 + row0) * Ddim;
    const size_t base1 = ((size_t)b * Nn + n0 + row1) * Ddim;
    if (slot == 2) {
        #pragma unroll
        for (int nb = 0; nb < 16; nb++) {
            const int d = nb * 8 + t * 2;
            *(__half2*)&g_V[base0 + d] = __floats2half2_rn(acc[nb][0], acc[nb][1]);
            *(__half2*)&g_V[base1 + d] = __floats2half2_rn(acc[nb][2], acc[nb][3]);
        }
    } else {
        __nv_bfloat16* Hh = (slot == 0) ? g_Qh : g_Kh;
        __nv_bfloat16* Hl = (slot == 0) ? g_Ql : g_Kl;
        #pragma unroll
        for (int nb = 0; nb < 16; nb++) {
            const int d = nb * 8 + t * 2;
            __nv_bfloat162 h0, l0, h1, l1;
            h0.x = __float2bfloat16_rn(acc[nb][0]);
            h0.y = __float2bfloat16_rn(acc[nb][1]);
            l0.x = __float2bfloat16_rn(acc[nb][0] - __bfloat162float(h0.x));
            l0.y = __float2bfloat16_rn(acc[nb][1] - __bfloat162float(h0.y));
            h1.x = __float2bfloat16_rn(acc[nb][2]);
            h1.y = __float2bfloat16_rn(acc[nb][3]);
            l1.x = __float2bfloat16_rn(acc[nb][2] - __bfloat162float(h1.x));
            l1.y = __float2bfloat16_rn(acc[nb][3] - __bfloat162float(h1.y));
            *(__nv_bfloat162*)&Hh[base0 + d] = h0;
            *(__nv_bfloat162*)&Hl[base0 + d] = l0;
            *(__nv_bfloat162*)&Hh[base1 + d] = h1;
            *(__nv_bfloat162*)&Hl[base1 + d] = l1;
        }
    }
}

// ---------------------------------------------------------------------------
// Kernel 2: flash attention (R8/R10 shape: 256 thr, 8 warps, q-tile 128).
// S = QK^T: bf16 3-split via LDSM (unchanged). Softmax with running max.
// PV: fp16 m16n8k16 — P packed half2 in C-frag positions (A-frags via ldsm4),
// V fp16 row-major [key][d] loaded as B-frags via ldsm4.trans.
// All SMEM rows 68-word stride (272B = 17x16B units -> LDSM conflict-free).
// ---------------------------------------------------------------------------
#define QW 68
#define A_QH 0
#define A_QL (128 * QW)
#define A_KH (2 * 128 * QW)
#define A_KL (A_KH + 64 * QW)
#define A_VS (A_KL + 64 * QW)
#define A_PS (A_VS + 64 * QW)
#define ATTN_WORDS (A_PS + 128 * QW)
#define ATTN_SMEM (ATTN_WORDS * 4)

__global__ void __launch_bounds__(256, 1) attn_kernel() {
    extern __shared__ float sm[];
    uint32_t* Qh = (uint32_t*)sm + A_QH;
    uint32_t* Ql = (uint32_t*)sm + A_QL;
    uint32_t* Kh = (uint32_t*)sm + A_KH;
    uint32_t* Kl = (uint32_t*)sm + A_KL;
    uint32_t* Vw = (uint32_t*)sm + A_VS;   // fp16 V [key][d], 64 words data/row
    uint32_t* Pw = (uint32_t*)sm + A_PS;   // fp16 P [row][key], 32 words data/row

    const uint32_t sb  = smem_u32(sm);
    const uint32_t bQH = sb + A_QH * 4;
    const uint32_t bQL = sb + A_QL * 4;
    const uint32_t bKH = sb + A_KH * 4;
    const uint32_t bKL = sb + A_KL * 4;
    const uint32_t bVS = sb + A_VS * 4;
    const uint32_t bPS = sb + A_PS * 4;

    const int b  = blockIdx.y;
    const int q0 = blockIdx.x * 128;
    const uint32_t* Qgh = (const uint32_t*)(g_Qh + ((size_t)b * Nn + q0) * Ddim);
    const uint32_t* Qgl = (const uint32_t*)(g_Ql + ((size_t)b * Nn + q0) * Ddim);
    const uint32_t* Kgh = (const uint32_t*)(g_Kh + (size_t)b * Nn * Ddim);
    const uint32_t* Kgl = (const uint32_t*)(g_Kl + (size_t)b * Nn * Ddim);
    const uint32_t* Vg  = (const uint32_t*)(g_V + (size_t)b * Nn * Ddim);

    const int tid  = threadIdx.x;
    const int lane = tid & 31;
    const int w    = tid >> 5;
    const int g    = lane >> 2;
    const int t    = lane & 3;

    // ldmatrix per-thread address offsets (bytes)
    const uint32_t aOff = ((uint32_t)(w * 16 + (lane & 7) + ((lane >> 3) & 1) * 8) * QW
                          + (lane >> 4) * 4) * 4;
    const uint32_t bOff = ((uint32_t)((lane >> 4) * 8 + (lane & 7)) * QW
                          + ((lane >> 3) & 1) * 4) * 4;
    // V B-frag (trans): row-within-tile (keys) + n-chunk selector
    const uint32_t vOff = ((uint32_t)((lane & 7) + ((lane >> 3) & 1) * 8) * QW
                          + (lane >> 4) * 4) * 4;

    #pragma unroll
    for (int i = 0; i < 8; i++) {
        int f = tid + i * 256;
        int r = f >> 4, cw = (f & 15) * 4;
        *(uint4*)&Qh[r * QW + cw] = *(const uint4*)&Qgh[r * 64 + cw];
        *(uint4*)&Ql[r * QW + cw] = *(const uint4*)&Qgl[r * 64 + cw];
    }

    float m0 = -1e30f, m1 = -1e30f, l0 = 0.f, l1 = 0.f;
    float o[16][4];
    #pragma unroll
    for (int nb = 0; nb < 16; nb++)
        #pragma unroll
        for (int c = 0; c < 4; c++) o[nb][c] = 0.f;

    const int row0 = w * 16 + g;
    const int row1 = row0 + 8;

    for (int j0 = 0; j0 < Nn; j0 += 64) {
        __syncthreads();
        // Stage K hi/lo (1024 uint4 each) and V fp16 (1024 uint4)
        #pragma unroll
        for (int i = 0; i < 4; i++) {
            int f = tid + i * 256;
            int r = f >> 4, cw = (f & 15) * 4;
            *(uint4*)&Kh[r * QW + cw] = *(const uint4*)&Kgh[(size_t)(j0 + r) * 64 + cw];
            *(uint4*)&Kl[r * QW + cw] = *(const uint4*)&Kgl[(size_t)(j0 + r) * 64 + cw];
        }
        #pragma unroll
        for (int i = 0; i < 4; i++) {
            int f = tid + i * 256;
            int r = f >> 4, cw = (f & 15) * 4;
            *(uint4*)&Vw[r * QW + cw] = *(const uint4*)&Vg[(size_t)(j0 + r) * 64 + cw];
        }
        __syncthreads();

        // ---- S = Q K^T via ldmatrix fragments (bf16 3-split, unchanged) ----
        float s[8][4];
        #pragma unroll
        for (int nb = 0; nb < 8; nb++)
            #pragma unroll
            for (int c = 0; c < 4; c++) s[nb][c] = 0.f;

        #pragma unroll
        for (int kb = 0; kb < 8; kb++) {
            const uint32_t kByte = kb * 32;
            uint32_t ah[4], al[4];
            ldsm4(ah, bQH + aOff + kByte);
            ldsm4(al, bQL + aOff + kByte);
            #pragma unroll
            for (int nbp = 0; nbp < 4; nbp++) {
                const uint32_t bo = bOff + (uint32_t)nbp * 16 * QW * 4 + kByte;
                uint32_t bh[4], bl[4];
                ldsm4(bh, bKH + bo);
                ldsm4(bl, bKL + bo);
                mma16(s[2 * nbp],     ah, &bh[0]);
                mma16(s[2 * nbp],     ah, &bl[0]);
                mma16(s[2 * nbp],     al, &bh[0]);
                mma16(s[2 * nbp + 1], ah, &bh[2]);
                mma16(s[2 * nbp + 1], ah, &bl[2]);
                mma16(s[2 * nbp + 1], al, &bh[2]);
            }
        }

        // ---- online softmax with running max (R8-proven) ----
        float mx0 = -1e30f, mx1 = -1e30f;
        #pragma unroll
        for (int nb = 0; nb < 8; nb++) {
            mx0 = fmaxf(mx0, fmaxf(s[nb][0], s[nb][1]));
            mx1 = fmaxf(mx1, fmaxf(s[nb][2], s[nb][3]));
        }
        mx0 = fmaxf(mx0, __shfl_xor_sync(0xffffffffu, mx0, 1));
        mx0 = fmaxf(mx0, __shfl_xor_sync(0xffffffffu, mx0, 2));
        mx1 = fmaxf(mx1, __shfl_xor_sync(0xffffffffu, mx1, 1));
        mx1 = fmaxf(mx1, __shfl_xor_sync(0xffffffffu, mx1, 2));
        float mn0 = fmaxf(m0, mx0), mn1 = fmaxf(m1, mx1);
        float sc0 = __expf(m0 - mn0), sc1 = __expf(m1 - mn1);
        m0 = mn0; m1 = mn1;
        l0 *= sc0; l1 *= sc1;
        #pragma unroll
        for (int nb = 0; nb < 16; nb++) {
            o[nb][0] *= sc0; o[nb][1] *= sc0;
            o[nb][2] *= sc1; o[nb][3] *= sc1;
        }
        float rs0 = 0.f, rs1 = 0.f;
        #pragma unroll
        for (int nb = 0; nb < 8; nb++) {
            float p0 = __expf(s[nb][0] - mn0);
            float p1 = __expf(s[nb][1] - mn0);
            float p2 = __expf(s[nb][2] - mn1);
            float p3 = __expf(s[nb][3] - mn1);
            rs0 += p0 + p1;
            rs1 += p2 + p3;
            __half2 hp0 = __floats2half2_rn(p0, p1);
            __half2 hp1 = __floats2half2_rn(p2, p3);
            *(__half2*)&Pw[row0 * QW + nb * 4 + t] = hp0;
            *(__half2*)&Pw[row1 * QW + nb * 4 + t] = hp1;
        }
        rs0 += __shfl_xor_sync(0xffffffffu, rs0, 1);
        rs0 += __shfl_xor_sync(0xffffffffu, rs0, 2);
        rs1 += __shfl_xor_sync(0xffffffffu, rs1, 1);
        rs1 += __shfl_xor_sync(0xffffffffu, rs1, 2);
        l0 += rs0; l1 += rs1;
        __syncwarp();  // P rows are warp-private: order STS -> LDSM within warp

        // ---- O += P V : fp16 m16n8k16 (A = P via ldsm4, B = V via ldsm4t) ----
        #pragma unroll
        for (int kb = 0; kb < 4; kb++) {
            uint32_t pa[4];
            ldsm4(pa, bPS + aOff + kb * 32);
            #pragma unroll
            for (int nbp = 0; nbp < 8; nbp++) {
                uint32_t vb[4];
                ldsm4t(vb, bVS + vOff + (uint32_t)kb * 16 * QW * 4 + nbp * 32);
                mma16h(o[2 * nbp],     pa, &vb[0]);
                mma16h(o[2 * nbp + 1], pa, &vb[2]);
            }
        }
    }

    // Normalize and write Y as bf16 hi/lo split
    float inv0 = 1.f / l0, inv1 = 1.f / l1;
    const size_t base0 = ((size_t)b * Nn + q0 + row0) * Ddim;
    const size_t base1 = ((size_t)b * Nn + q0 + row1) * Ddim;
    #pragma unroll
    for (int nb = 0; nb < 16; nb++) {
        const int d = nb * 8 + t * 2;
        float y00 = o[nb][0] * inv0, y01 = o[nb][1] * inv0;
        float y10 = o[nb][2] * inv1, y11 = o[nb][3] * inv1;
        __nv_bfloat162 h0, l0v, h1, l1v;
        h0.x = __float2bfloat16_rn(y00);
        h0.y = __float2bfloat16_rn(y01);
        l0v.x = __float2bfloat16_rn(y00 - __bfloat162float(h0.x));
        l0v.y = __float2bfloat16_rn(y01 - __bfloat162float(h0.y));
        h1.x = __float2bfloat16_rn(y10);
        h1.y = __float2bfloat16_rn(y11);
        l1v.x = __float2bfloat16_rn(y10 - __bfloat162float(h1.x));
        l1v.y = __float2bfloat16_rn(y11 - __bfloat162float(h1.y));
        *(__nv_bfloat162*)&g_Yh[base0 + d] = h0;
        *(__nv_bfloat162*)&g_Yl[base0 + d] = l0v;
        *(__nv_bfloat162*)&g_Yh[base1 + d] = h1;
        *(__nv_bfloat162*)&g_Yl[base1 + d] = l1v;
    }
}

// ---------------------------------------------------------------------------
// Kernel 3: out = x + w_out * y on tensor cores (unchanged).
// ---------------------------------------------------------------------------
#define OUT_AH 0
#define OUT_AL (128 * P36)
#define OUT_BH (2 * 128 * P36)
#define OUT_BL (2 * 128 * P36 + 64 * P36)
#define OUT_SMEM ((2 * 128 * P36 + 2 * 64 * P36) * 4)

__global__ void __launch_bounds__(256) out_tc_kernel(const float* __restrict__ x,
                                                     float* __restrict__ out) {
    extern __shared__ uint32_t S[];
    const int b = blockIdx.z, c0 = blockIdx.y * 128, n0 = blockIdx.x * 64;
    const int tid = threadIdx.x;
    const int lane = tid & 31, w = tid >> 5;
    const int g = lane >> 2, t = lane & 3;
    const int row0 = w * 16 + g, row1 = row0 + 8;

    const uint32_t* Ahw = (const uint32_t*)(g_Wh + 3 * 32768);
    const uint32_t* Alw = (const uint32_t*)(g_Wl + 3 * 32768);
    const uint32_t* Bhw = (const uint32_t*)g_Yh;
    const uint32_t* Blw = (const uint32_t*)g_Yl;

    float acc[8][4];
    #pragma unroll
    for (int nb = 0; nb < 8; nb++)
        #pragma unroll
        for (int c = 0; c < 4; c++) acc[nb][c] = 0.f;

    for (int chunk = 0; chunk < 2; chunk++) {
        const int dd0 = chunk * 64;
        __syncthreads();
        #pragma unroll
        for (int i = 0; i < 4; i++) {
            int f = tid + i * 256;
            int r = f >> 3, w4 = (f & 7) * 4;
            int ab = (c0 + r) * 64 + (dd0 >> 1);
            *(uint4*)&S[OUT_AH + r * P36 + w4] = *(const uint4*)&Ahw[ab + w4];
            *(uint4*)&S[OUT_AL + r * P36 + w4] = *(const uint4*)&Alw[ab + w4];
        }
        #pragma unroll
        for (int i = 0; i < 2; i++) {
            int f = tid + i * 256;
            int r = f >> 3, w4 = (f & 7) * 4;
            size_t bb = ((size_t)(b * Nn + n0 + r) * Ddim + dd0) >> 1;
            *(uint4*)&S[OUT_BH + r * P36 + w4] = *(const uint4*)&Bhw[bb + w4];
            *(uint4*)&S[OUT_BL + r * P36 + w4] = *(const uint4*)&Blw[bb + w4];
        }
        __syncthreads();

        #pragma unroll
        for (int kb = 0; kb < 4; kb++) {
            const int kw = kb * 8 + t;
            uint32_t ah[4], al[4];
            ah[0] = S[OUT_AH + row0 * P36 + kw];
            ah[1] = S[OUT_AH + row1 * P36 + kw];
            ah[2] = S[OUT_AH + row0 * P36 + kw + 4];
            ah[3] = S[OUT_AH + row1 * P36 + kw + 4];
            al[0] = S[OUT_AL + row0 * P36 + kw];
            al[1] = S[OUT_AL + row1 * P36 + kw];
            al[2] = S[OUT_AL + row0 * P36 + kw + 4];
            al[3] = S[OUT_AL + row1 * P36 + kw + 4];
            #pragma unroll
            for (int nb = 0; nb < 8; nb++) {
                const int rr = nb * 8 + g;
                uint32_t bh[2], bl[2];
                bh[0] = S[OUT_BH + rr * P36 + kw];
                bh[1] = S[OUT_BH + rr * P36 + kw + 4];
                bl[0] = S[OUT_BL + rr * P36 + kw];
                bl[1] = S[OUT_BL + rr * P36 + kw + 4];
                mma16(acc[nb], ah, bh);
                mma16(acc[nb], ah, bl);
                mma16(acc[nb], al, bh);
            }
        }
    }

    const int ch0 = c0 + row0, ch1 = c0 + row1;
    #pragma unroll
    for (int nb = 0; nb < 8; nb++) {
        const int pix = n0 + nb * 8 + t * 2;
        size_t i0 = (size_t)b * Cdim * Nn + (size_t)ch0 * Nn + pix;
        size_t i1 = (size_t)b * Cdim * Nn + (size_t)ch1 * Nn + pix;
        float2 x0 = *(const float2*)&x[i0];
        float2 x1 = *(const float2*)&x[i1];
        *(float2*)&out[i0] = make_float2(x0.x + acc[nb][0], x0.y + acc[nb][1]);
        *(float2*)&out[i1] = make_float2(x1.x + acc[nb][2], x1.y + acc[nb][3]);
    }
}

// ---------------------------------------------------------------------------
extern "C" void kernel_launch(void* const* d_in, const int* in_sizes, int n_in,
                              void* d_out, int out_size) {
    const float* x  = (const float*)d_in[0];
    const float* wt = (const float*)d_in[1];
    const float* wp = (const float*)d_in[2];
    const float* wg = (const float*)d_in[3];
    const float* wo = (const float*)d_in[4];
    float* out = (float*)d_out;

    cudaFuncSetAttribute(attn_kernel,
                         cudaFuncAttributeMaxDynamicSharedMemorySize, ATTN_SMEM);
    cudaFuncSetAttribute(qkv_tc_kernel,
                         cudaFuncAttributeMaxDynamicSharedMemorySize, QKV_SMEM);
    cudaFuncSetAttribute(out_tc_kernel,
                         cudaFuncAttributeMaxDynamicSharedMemorySize, OUT_SMEM);

    split_w4_kernel<<<dim3(128, 4), 256>>>(wt, wp, wg, wo);
    xpose_kernel<<<dim3(Nn / 32, Cdim / 32, Bsz), 256>>>(x);
    qkv_tc_kernel<<<dim3(Nn / 128, 3, Bsz), 256, QKV_SMEM>>>();
    attn_kernel<<<dim3(Nn / 128, Bsz), 256, ATTN_SMEM>>>();
    out_tc_kernel<<<dim3(Nn / 64, Cdim / 128, Bsz), 256, OUT_SMEM>>>(x, out);
}

// round 14
// speedup vs baseline: 1.4399x; 1.0966x over previous
#include <cuda_runtime.h>
#include <cuda_bf16.h>
#include <cuda_fp16.h>
#include <cstdint>
#include <math.h>

#define Bsz  4
#define Cdim 256
#define Ddim 128
#define Nn   4096

// Scratch (static __device__ — no allocations allowed)
__device__ __half g_Q[Bsz * Nn * Ddim];                // fp16 rounded Q
__device__ __half g_KhA[Bsz * Nn * Ddim];              // fp16 K hi
__device__ __half g_KlA[Bsz * Nn * Ddim];              // fp16 K lo
__device__ __half g_V[Bsz * Nn * Ddim];                // fp16 V
__device__ __nv_bfloat16 g_Yh[Bsz * Nn * Ddim];
__device__ __nv_bfloat16 g_Yl[Bsz * Nn * Ddim];
__device__ __nv_bfloat16 g_Xth[Bsz * Nn * Cdim];       // x^T split
__device__ __nv_bfloat16 g_Xtl[Bsz * Nn * Cdim];
__device__ __nv_bfloat16 g_Wh[4 * 32768];              // wt,wp,wg,w_out split
__device__ __nv_bfloat16 g_Wl[4 * 32768];

__device__ __forceinline__ void mma16(float* c, const uint32_t* a, const uint32_t* b) {
    asm volatile(
        "mma.sync.aligned.m16n8k16.row.col.f32.bf16.bf16.f32 "
        "{%0,%1,%2,%3},{%4,%5,%6,%7},{%8,%9},{%0,%1,%2,%3};"
        : "+f"(c[0]), "+f"(c[1]), "+f"(c[2]), "+f"(c[3])
        : "r"(a[0]), "r"(a[1]), "r"(a[2]), "r"(a[3]), "r"(b[0]), "r"(b[1]));
}

__device__ __forceinline__ void mma16h(float* c, const uint32_t* a, const uint32_t* b) {
    asm volatile(
        "mma.sync.aligned.m16n8k16.row.col.f32.f16.f16.f32 "
        "{%0,%1,%2,%3},{%4,%5,%6,%7},{%8,%9},{%0,%1,%2,%3};"
        : "+f"(c[0]), "+f"(c[1]), "+f"(c[2]), "+f"(c[3])
        : "r"(a[0]), "r"(a[1]), "r"(a[2]), "r"(a[3]), "r"(b[0]), "r"(b[1]));
}

__device__ __forceinline__ void ldsm4(uint32_t* r, uint32_t addr) {
    asm volatile(
        "ldmatrix.sync.aligned.m8n8.x4.shared.b16 {%0,%1,%2,%3}, [%4];"
        : "=r"(r[0]), "=r"(r[1]), "=r"(r[2]), "=r"(r[3]) : "r"(addr));
}

__device__ __forceinline__ void ldsm4t(uint32_t* r, uint32_t addr) {
    asm volatile(
        "ldmatrix.sync.aligned.m8n8.x4.trans.shared.b16 {%0,%1,%2,%3}, [%4];"
        : "=r"(r[0]), "=r"(r[1]), "=r"(r[2]), "=r"(r[3]) : "r"(addr));
}

__device__ __forceinline__ uint32_t smem_u32(const void* p) {
    uint32_t a;
    asm("{ .reg .u64 t; cvta.to.shared.u64 t, %1; cvt.u32.u64 %0, t; }" : "=r"(a) : "l"(p));
    return a;
}

// ---------------------------------------------------------------------------
// Prep 1: split all 4 fp32 weights into bf16 hi/lo (one launch).
// ---------------------------------------------------------------------------
__global__ void split_w4_kernel(const float* __restrict__ w0, const float* __restrict__ w1,
                                const float* __restrict__ w2, const float* __restrict__ w3) {
    int slot = blockIdx.y;
    const float* src = (slot == 0) ? w0 : (slot == 1) ? w1 : (slot == 2) ? w2 : w3;
    int i = blockIdx.x * 256 + threadIdx.x;
    float v = src[i];
    __nv_bfloat16 h = __float2bfloat16_rn(v);
    __nv_bfloat16 l = __float2bfloat16_rn(v - __bfloat162float(h));
    g_Wh[slot * 32768 + i] = h;
    g_Wl[slot * 32768 + i] = l;
}

// ---------------------------------------------------------------------------
// Prep 2: transpose-split x[b][c][n] -> xt[b][n][c] bf16 hi/lo.
// ---------------------------------------------------------------------------
__global__ void xpose_kernel(const float* __restrict__ x) {
    __shared__ float tsm[32][33];
    const int b = blockIdx.z, n0 = blockIdx.x * 32, c0 = blockIdx.y * 32;
    const int tx = threadIdx.x & 31, ty = threadIdx.x >> 5;
    const float* xb = x + (size_t)b * Cdim * Nn;
    #pragma unroll
    for (int i = 0; i < 4; i++)
        tsm[ty + 8 * i][tx] = xb[(size_t)(c0 + ty + 8 * i) * Nn + n0 + tx];
    __syncthreads();
    #pragma unroll
    for (int i = 0; i < 4; i++) {
        float v = tsm[tx][ty + 8 * i];
        __nv_bfloat16 h = __float2bfloat16_rn(v);
        __nv_bfloat16 l = __float2bfloat16_rn(v - __bfloat162float(h));
        size_t o = ((size_t)b * Nn + n0 + ty + 8 * i) * Cdim + c0 + tx;
        g_Xth[o] = h;
        g_Xtl[o] = l;
    }
}

// ---------------------------------------------------------------------------
// Kernel 1: QKV projection on tensor cores.
// Epilogue: slot 0 -> Q fp16; slot 1 -> K fp16 hi/lo; slot 2 -> V fp16.
// ---------------------------------------------------------------------------
#define P36 36
#define QKV_XH 0
#define QKV_XL (128 * P36)
#define QKV_WH (2 * 128 * P36)
#define QKV_WL (3 * 128 * P36)
#define QKV_SMEM (4 * 128 * P36 * 4)

__global__ void __launch_bounds__(256, 1) qkv_tc_kernel() {
    extern __shared__ uint32_t S[];
    const int b = blockIdx.z, slot = blockIdx.y, n0 = blockIdx.x * 128;
    const int tid = threadIdx.x;
    const int lane = tid & 31, w = tid >> 5;
    const int g = lane >> 2, t = lane & 3;
    const int row0 = w * 16 + g, row1 = row0 + 8;

    const uint32_t* Xhw = (const uint32_t*)g_Xth;
    const uint32_t* Xlw = (const uint32_t*)g_Xtl;
    const uint32_t* Whw = (const uint32_t*)(g_Wh + slot * 32768);
    const uint32_t* Wlw = (const uint32_t*)(g_Wl + slot * 32768);

    float acc[16][4];
    #pragma unroll
    for (int nb = 0; nb < 16; nb++)
        #pragma unroll
        for (int c = 0; c < 4; c++) acc[nb][c] = 0.f;

    for (int chunk = 0; chunk < 4; chunk++) {
        const int c0 = chunk * 64;
        __syncthreads();
        #pragma unroll
        for (int i = 0; i < 4; i++) {
            int f = tid + i * 256;
            int r = f >> 3, w4 = (f & 7) * 4;
            size_t xb = ((size_t)(b * Nn + n0 + r) * Cdim + c0) >> 1;
            *(uint4*)&S[QKV_XH + r * P36 + w4] = *(const uint4*)&Xhw[xb + w4];
            *(uint4*)&S[QKV_XL + r * P36 + w4] = *(const uint4*)&Xlw[xb + w4];
            int wb = r * 128 + (c0 >> 1);
            *(uint4*)&S[QKV_WH + r * P36 + w4] = *(const uint4*)&Whw[wb + w4];
            *(uint4*)&S[QKV_WL + r * P36 + w4] = *(const uint4*)&Wlw[wb + w4];
        }
        __syncthreads();

        #pragma unroll
        for (int kb = 0; kb < 4; kb++) {
            const int kw = kb * 8 + t;
            uint32_t ah[4], al[4];
            ah[0] = S[QKV_XH + row0 * P36 + kw];
            ah[1] = S[QKV_XH + row1 * P36 + kw];
            ah[2] = S[QKV_XH + row0 * P36 + kw + 4];
            ah[3] = S[QKV_XH + row1 * P36 + kw + 4];
            al[0] = S[QKV_XL + row0 * P36 + kw];
            al[1] = S[QKV_XL + row1 * P36 + kw];
            al[2] = S[QKV_XL + row0 * P36 + kw + 4];
            al[3] = S[QKV_XL + row1 * P36 + kw + 4];
            #pragma unroll
            for (int nb = 0; nb < 16; nb++) {
                const int rr = nb * 8 + g;
                uint32_t bh[2], bl[2];
                bh[0] = S[QKV_WH + rr * P36 + kw];
                bh[1] = S[QKV_WH + rr * P36 + kw + 4];
                bl[0] = S[QKV_WL + rr * P36 + kw];
                bl[1] = S[QKV_WL + rr * P36 + kw + 4];
                mma16(acc[nb], ah, bh);
                mma16(acc[nb], ah, bl);
                mma16(acc[nb], al, bh);
            }
        }
    }

    const size_t base0 = ((size_t)b * Nn + n0 + row0) * Ddim;
    const size_t base1 = ((size_t)b * Nn + n0 + row1) * Ddim;
    if (slot == 0) {
        #pragma unroll
        for (int nb = 0; nb < 16; nb++) {
            const int d = nb * 8 + t * 2;
            *(__half2*)&g_Q[base0 + d] = __floats2half2_rn(acc[nb][0], acc[nb][1]);
            *(__half2*)&g_Q[base1 + d] = __floats2half2_rn(acc[nb][2], acc[nb][3]);
        }
    } else if (slot == 2) {
        #pragma unroll
        for (int nb = 0; nb < 16; nb++) {
            const int d = nb * 8 + t * 2;
            *(__half2*)&g_V[base0 + d] = __floats2half2_rn(acc[nb][0], acc[nb][1]);
            *(__half2*)&g_V[base1 + d] = __floats2half2_rn(acc[nb][2], acc[nb][3]);
        }
    } else {
        #pragma unroll
        for (int nb = 0; nb < 16; nb++) {
            const int d = nb * 8 + t * 2;
            __half h00 = __float2half_rn(acc[nb][0]);
            __half h01 = __float2half_rn(acc[nb][1]);
            __half h10 = __float2half_rn(acc[nb][2]);
            __half h11 = __float2half_rn(acc[nb][3]);
            __half l00 = __float2half_rn(acc[nb][0] - __half2float(h00));
            __half l01 = __float2half_rn(acc[nb][1] - __half2float(h01));
            __half l10 = __float2half_rn(acc[nb][2] - __half2float(h10));
            __half l11 = __float2half_rn(acc[nb][3] - __half2float(h11));
            *(__half2*)&g_KhA[base0 + d] = __halves2half2(h00, h01);
            *(__half2*)&g_KhA[base1 + d] = __halves2half2(h10, h11);
            *(__half2*)&g_KlA[base0 + d] = __halves2half2(l00, l01);
            *(__half2*)&g_KlA[base1 + d] = __halves2half2(l10, l11);
        }
    }
}

// ---------------------------------------------------------------------------
// Kernel 2: flash attention. All-fp16 MMA path:
// S = q16 · (Kh + Kl): fp16 2-split, 128 MMAs/warp/tile.
// PV: fp16 m16n8k16 (P half2 C-frag positions, V via ldsm4.trans) — R12-proven.
// FIX vs R13: Q staging covers all 128 rows (2048 uint4 -> 8 iterations).
// ---------------------------------------------------------------------------
#define QW 68
#define A_Q  0
#define A_KH (128 * QW)
#define A_KL (A_KH + 64 * QW)
#define A_VS (A_KL + 64 * QW)
#define A_PS (A_VS + 64 * QW)
#define ATTN_WORDS (A_PS + 128 * QW)
#define ATTN_SMEM (ATTN_WORDS * 4)

__global__ void __launch_bounds__(256, 1) attn_kernel() {
    extern __shared__ float sm[];
    uint32_t* Qs = (uint32_t*)sm + A_Q;
    uint32_t* Kh = (uint32_t*)sm + A_KH;
    uint32_t* Kl = (uint32_t*)sm + A_KL;
    uint32_t* Vw = (uint32_t*)sm + A_VS;
    uint32_t* Pw = (uint32_t*)sm + A_PS;

    const uint32_t sb  = smem_u32(sm);
    const uint32_t bQS = sb + A_Q * 4;
    const uint32_t bKH = sb + A_KH * 4;
    const uint32_t bKL = sb + A_KL * 4;
    const uint32_t bVS = sb + A_VS * 4;
    const uint32_t bPS = sb + A_PS * 4;

    const int b  = blockIdx.y;
    const int q0 = blockIdx.x * 128;
    const uint32_t* Qg  = (const uint32_t*)(g_Q + ((size_t)b * Nn + q0) * Ddim);
    const uint32_t* Kgh = (const uint32_t*)(g_KhA + (size_t)b * Nn * Ddim);
    const uint32_t* Kgl = (const uint32_t*)(g_KlA + (size_t)b * Nn * Ddim);
    const uint32_t* Vg  = (const uint32_t*)(g_V + (size_t)b * Nn * Ddim);

    const int tid  = threadIdx.x;
    const int lane = tid & 31;
    const int w    = tid >> 5;
    const int g    = lane >> 2;
    const int t    = lane & 3;

    const uint32_t aOff = ((uint32_t)(w * 16 + (lane & 7) + ((lane >> 3) & 1) * 8) * QW
                          + (lane >> 4) * 4) * 4;
    const uint32_t bOff = ((uint32_t)((lane >> 4) * 8 + (lane & 7)) * QW
                          + ((lane >> 3) & 1) * 4) * 4;
    const uint32_t vOff = ((uint32_t)((lane & 7) + ((lane >> 3) & 1) * 8) * QW
                          + (lane >> 4) * 4) * 4;

    // Q: 128 rows x 16 uint4 = 2048 uint4 -> 8 iterations of 256 threads
    #pragma unroll
    for (int i = 0; i < 8; i++) {
        int f = tid + i * 256;
        int r = f >> 4, cw = (f & 15) * 4;
        *(uint4*)&Qs[r * QW + cw] = *(const uint4*)&Qg[r * 16 * 4 + cw];
    }

    float m0 = -1e30f, m1 = -1e30f, l0 = 0.f, l1 = 0.f;
    float o[16][4];
    #pragma unroll
    for (int nb = 0; nb < 16; nb++)
        #pragma unroll
        for (int c = 0; c < 4; c++) o[nb][c] = 0.f;

    const int row0 = w * 16 + g;
    const int row1 = row0 + 8;

    for (int j0 = 0; j0 < Nn; j0 += 64) {
        __syncthreads();
        #pragma unroll
        for (int i = 0; i < 4; i++) {
            int f = tid + i * 256;
            int r = f >> 4, cw = (f & 15) * 4;
            *(uint4*)&Kh[r * QW + cw] = *(const uint4*)&Kgh[(size_t)(j0 + r) * 64 + cw];
            *(uint4*)&Kl[r * QW + cw] = *(const uint4*)&Kgl[(size_t)(j0 + r) * 64 + cw];
        }
        #pragma unroll
        for (int i = 0; i < 4; i++) {
            int f = tid + i * 256;
            int r = f >> 4, cw = (f & 15) * 4;
            *(uint4*)&Vw[r * QW + cw] = *(const uint4*)&Vg[(size_t)(j0 + r) * 64 + cw];
        }
        __syncthreads();

        // ---- S = Q (Kh + Kl): fp16 2-split via ldmatrix ----
        float s[8][4];
        #pragma unroll
        for (int nb = 0; nb < 8; nb++)
            #pragma unroll
            for (int c = 0; c < 4; c++) s[nb][c] = 0.f;

        #pragma unroll
        for (int kb = 0; kb < 8; kb++) {
            const uint32_t kByte = kb * 32;
            uint32_t ah[4];
            ldsm4(ah, bQS + aOff + kByte);
            #pragma unroll
            for (int nbp = 0; nbp < 4; nbp++) {
                const uint32_t bo = bOff + (uint32_t)nbp * 16 * QW * 4 + kByte;
                uint32_t bh[4], bl[4];
                ldsm4(bh, bKH + bo);
                ldsm4(bl, bKL + bo);
                mma16h(s[2 * nbp],     ah, &bh[0]);
                mma16h(s[2 * nbp],     ah, &bl[0]);
                mma16h(s[2 * nbp + 1], ah, &bh[2]);
                mma16h(s[2 * nbp + 1], ah, &bl[2]);
            }
        }

        // ---- online softmax with running max ----
        float mx0 = -1e30f, mx1 = -1e30f;
        #pragma unroll
        for (int nb = 0; nb < 8; nb++) {
            mx0 = fmaxf(mx0, fmaxf(s[nb][0], s[nb][1]));
            mx1 = fmaxf(mx1, fmaxf(s[nb][2], s[nb][3]));
        }
        mx0 = fmaxf(mx0, __shfl_xor_sync(0xffffffffu, mx0, 1));
        mx0 = fmaxf(mx0, __shfl_xor_sync(0xffffffffu, mx0, 2));
        mx1 = fmaxf(mx1, __shfl_xor_sync(0xffffffffu, mx1, 1));
        mx1 = fmaxf(mx1, __shfl_xor_sync(0xffffffffu, mx1, 2));
        float mn0 = fmaxf(m0, mx0), mn1 = fmaxf(m1, mx1);
        float sc0 = __expf(m0 - mn0), sc1 = __expf(m1 - mn1);
        m0 = mn0; m1 = mn1;
        l0 *= sc0; l1 *= sc1;
        #pragma unroll
        for (int nb = 0; nb < 16; nb++) {
            o[nb][0] *= sc0; o[nb][1] *= sc0;
            o[nb][2] *= sc1; o[nb][3] *= sc1;
        }
        float rs0 = 0.f, rs1 = 0.f;
        #pragma unroll
        for (int nb = 0; nb < 8; nb++) {
            float p0 = __expf(s[nb][0] - mn0);
            float p1 = __expf(s[nb][1] - mn0);
            float p2 = __expf(s[nb][2] - mn1);
            float p3 = __expf(s[nb][3] - mn1);
            rs0 += p0 + p1;
            rs1 += p2 + p3;
            __half2 hp0 = __floats2half2_rn(p0, p1);
            __half2 hp1 = __floats2half2_rn(p2, p3);
            *(__half2*)&Pw[row0 * QW + nb * 4 + t] = hp0;
            *(__half2*)&Pw[row1 * QW + nb * 4 + t] = hp1;
        }
        rs0 += __shfl_xor_sync(0xffffffffu, rs0, 1);
        rs0 += __shfl_xor_sync(0xffffffffu, rs0, 2);
        rs1 += __shfl_xor_sync(0xffffffffu, rs1, 1);
        rs1 += __shfl_xor_sync(0xffffffffu, rs1, 2);
        l0 += rs0; l1 += rs1;
        __syncwarp();  // P rows warp-private: order STS -> LDSM within warp

        // ---- O += P V : fp16 m16n8k16 ----
        #pragma unroll
        for (int kb = 0; kb < 4; kb++) {
            uint32_t pa[4];
            ldsm4(pa, bPS + aOff + kb * 32);
            #pragma unroll
            for (int nbp = 0; nbp < 8; nbp++) {
                uint32_t vb[4];
                ldsm4t(vb, bVS + vOff + (uint32_t)kb * 16 * QW * 4 + nbp * 32);
                mma16h(o[2 * nbp],     pa, &vb[0]);
                mma16h(o[2 * nbp + 1], pa, &vb[2]);
            }
        }
    }

    // Normalize and write Y as bf16 hi/lo split
    float inv0 = 1.f / l0, inv1 = 1.f / l1;
    const size_t base0 = ((size_t)b * Nn + q0 + row0) * Ddim;
    const size_t base1 = ((size_t)b * Nn + q0 + row1) * Ddim;
    #pragma unroll
    for (int nb = 0; nb < 16; nb++) {
        const int d = nb * 8 + t * 2;
        float y00 = o[nb][0] * inv0, y01 = o[nb][1] * inv0;
        float y10 = o[nb][2] * inv1, y11 = o[nb][3] * inv1;
        __nv_bfloat162 h0, l0v, h1, l1v;
        h0.x = __float2bfloat16_rn(y00);
        h0.y = __float2bfloat16_rn(y01);
        l0v.x = __float2bfloat16_rn(y00 - __bfloat162float(h0.x));
        l0v.y = __float2bfloat16_rn(y01 - __bfloat162float(h0.y));
        h1.x = __float2bfloat16_rn(y10);
        h1.y = __float2bfloat16_rn(y11);
        l1v.x = __float2bfloat16_rn(y10 - __bfloat162float(h1.x));
        l1v.y = __float2bfloat16_rn(y11 - __bfloat162float(h1.y));
        *(__nv_bfloat162*)&g_Yh[base0 + d] = h0;
        *(__nv_bfloat162*)&g_Yl[base0 + d] = l0v;
        *(__nv_bfloat162*)&g_Yh[base1 + d] = h1;
        *(__nv_bfloat162*)&g_Yl[base1 + d] = l1v;
    }
}

// ---------------------------------------------------------------------------
// Kernel 3: out = x + w_out * y on tensor cores (unchanged).
// ---------------------------------------------------------------------------
#define OUT_AH 0
#define OUT_AL (128 * P36)
#define OUT_BH (2 * 128 * P36)
#define OUT_BL (2 * 128 * P36 + 64 * P36)
#define OUT_SMEM ((2 * 128 * P36 + 2 * 64 * P36) * 4)

__global__ void __launch_bounds__(256) out_tc_kernel(const float* __restrict__ x,
                                                     float* __restrict__ out) {
    extern __shared__ uint32_t S[];
    const int b = blockIdx.z, c0 = blockIdx.y * 128, n0 = blockIdx.x * 64;
    const int tid = threadIdx.x;
    const int lane = tid & 31, w = tid >> 5;
    const int g = lane >> 2, t = lane & 3;
    const int row0 = w * 16 + g, row1 = row0 + 8;

    const uint32_t* Ahw = (const uint32_t*)(g_Wh + 3 * 32768);
    const uint32_t* Alw = (const uint32_t*)(g_Wl + 3 * 32768);
    const uint32_t* Bhw = (const uint32_t*)g_Yh;
    const uint32_t* Blw = (const uint32_t*)g_Yl;

    float acc[8][4];
    #pragma unroll
    for (int nb = 0; nb < 8; nb++)
        #pragma unroll
        for (int c = 0; c < 4; c++) acc[nb][c] = 0.f;

    for (int chunk = 0; chunk < 2; chunk++) {
        const int dd0 = chunk * 64;
        __syncthreads();
        #pragma unroll
        for (int i = 0; i < 4; i++) {
            int f = tid + i * 256;
            int r = f >> 3, w4 = (f & 7) * 4;
            int ab = (c0 + r) * 64 + (dd0 >> 1);
            *(uint4*)&S[OUT_AH + r * P36 + w4] = *(const uint4*)&Ahw[ab + w4];
            *(uint4*)&S[OUT_AL + r * P36 + w4] = *(const uint4*)&Alw[ab + w4];
        }
        #pragma unroll
        for (int i = 0; i < 2; i++) {
            int f = tid + i * 256;
            int r = f >> 3, w4 = (f & 7) * 4;
            size_t bb = ((size_t)(b * Nn + n0 + r) * Ddim + dd0) >> 1;
            *(uint4*)&S[OUT_BH + r * P36 + w4] = *(const uint4*)&Bhw[bb + w4];
            *(uint4*)&S[OUT_BL + r * P36 + w4] = *(const uint4*)&Blw[bb + w4];
        }
        __syncthreads();

        #pragma unroll
        for (int kb = 0; kb < 4; kb++) {
            const int kw = kb * 8 + t;
            uint32_t ah[4], al[4];
            ah[0] = S[OUT_AH + row0 * P36 + kw];
            ah[1] = S[OUT_AH + row1 * P36 + kw];
            ah[2] = S[OUT_AH + row0 * P36 + kw + 4];
            ah[3] = S[OUT_AH + row1 * P36 + kw + 4];
            al[0] = S[OUT_AL + row0 * P36 + kw];
            al[1] = S[OUT_AL + row1 * P36 + kw];
            al[2] = S[OUT_AL + row0 * P36 + kw + 4];
            al[3] = S[OUT_AL + row1 * P36 + kw + 4];
            #pragma unroll
            for (int nb = 0; nb < 8; nb++) {
                const int rr = nb * 8 + g;
                uint32_t bh[2], bl[2];
                bh[0] = S[OUT_BH + rr * P36 + kw];
                bh[1] = S[OUT_BH + rr * P36 + kw + 4];
                bl[0] = S[OUT_BL + rr * P36 + kw];
                bl[1] = S[OUT_BL + rr * P36 + kw + 4];
                mma16(acc[nb], ah, bh);
                mma16(acc[nb], ah, bl);
                mma16(acc[nb], al, bh);
            }
        }
    }

    const int ch0 = c0 + row0, ch1 = c0 + row1;
    #pragma unroll
    for (int nb = 0; nb < 8; nb++) {
        const int pix = n0 + nb * 8 + t * 2;
        size_t i0 = (size_t)b * Cdim * Nn + (size_t)ch0 * Nn + pix;
        size_t i1 = (size_t)b * Cdim * Nn + (size_t)ch1 * Nn + pix;
        float2 x0 = *(const float2*)&x[i0];
        float2 x1 = *(const float2*)&x[i1];
        *(float2*)&out[i0] = make_float2(x0.x + acc[nb][0], x0.y + acc[nb][1]);
        *(float2*)&out[i1] = make_float2(x1.x + acc[nb][2], x1.y + acc[nb][3]);
    }
}

// ---------------------------------------------------------------------------
extern "C" void kernel_launch(void* const* d_in, const int* in_sizes, int n_in,
                              void* d_out, int out_size) {
    const float* x  = (const float*)d_in[0];
    const float* wt = (const float*)d_in[1];
    const float* wp = (const float*)d_in[2];
    const float* wg = (const float*)d_in[3];
    const float* wo = (const float*)d_in[4];
    float* out = (float*)d_out;

    cudaFuncSetAttribute(attn_kernel,
                         cudaFuncAttributeMaxDynamicSharedMemorySize, ATTN_SMEM);
    cudaFuncSetAttribute(qkv_tc_kernel,
                         cudaFuncAttributeMaxDynamicSharedMemorySize, QKV_SMEM);
    cudaFuncSetAttribute(out_tc_kernel,
                         cudaFuncAttributeMaxDynamicSharedMemorySize, OUT_SMEM);

    split_w4_kernel<<<dim3(128, 4), 256>>>(wt, wp, wg, wo);
    xpose_kernel<<<dim3(Nn / 32, Cdim / 32, Bsz), 256>>>(x);
    qkv_tc_kernel<<<dim3(Nn / 128, 3, Bsz), 256, QKV_SMEM>>>();
    attn_kernel<<<dim3(Nn / 128, Bsz), 256, ATTN_SMEM>>>();
    out_tc_kernel<<<dim3(Nn / 64, Cdim / 128, Bsz), 256, OUT_SMEM>>>(x, out);
}

// round 15
// speedup vs baseline: 1.5240x; 1.0584x over previous
#include <cuda_runtime.h>
#include <cuda_bf16.h>
#include <cuda_fp16.h>
#include <cstdint>
#include <math.h>

#define Bsz  4
#define Cdim 256
#define Ddim 128
#define Nn   4096

// Scratch (static __device__ — no allocations allowed)
__device__ __half g_Q[Bsz * Nn * Ddim];                // fp16 rounded Q
__device__ __half g_KhA[Bsz * Nn * Ddim];              // fp16 K hi
__device__ __half g_KlA[Bsz * Nn * Ddim];              // fp16 K lo
__device__ __half g_V[Bsz * Nn * Ddim];                // fp16 V
__device__ __nv_bfloat16 g_Yh[Bsz * Nn * Ddim];
__device__ __nv_bfloat16 g_Yl[Bsz * Nn * Ddim];
__device__ __nv_bfloat16 g_Xth[Bsz * Nn * Cdim];       // x^T split
__device__ __nv_bfloat16 g_Xtl[Bsz * Nn * Cdim];
__device__ __nv_bfloat16 g_Wh[4 * 32768];              // wt,wp,wg,w_out split
__device__ __nv_bfloat16 g_Wl[4 * 32768];

__device__ __forceinline__ void mma16(float* c, const uint32_t* a, const uint32_t* b) {
    asm volatile(
        "mma.sync.aligned.m16n8k16.row.col.f32.bf16.bf16.f32 "
        "{%0,%1,%2,%3},{%4,%5,%6,%7},{%8,%9},{%0,%1,%2,%3};"
        : "+f"(c[0]), "+f"(c[1]), "+f"(c[2]), "+f"(c[3])
        : "r"(a[0]), "r"(a[1]), "r"(a[2]), "r"(a[3]), "r"(b[0]), "r"(b[1]));
}

__device__ __forceinline__ void mma16h(float* c, const uint32_t* a, const uint32_t* b) {
    asm volatile(
        "mma.sync.aligned.m16n8k16.row.col.f32.f16.f16.f32 "
        "{%0,%1,%2,%3},{%4,%5,%6,%7},{%8,%9},{%0,%1,%2,%3};"
        : "+f"(c[0]), "+f"(c[1]), "+f"(c[2]), "+f"(c[3])
        : "r"(a[0]), "r"(a[1]), "r"(a[2]), "r"(a[3]), "r"(b[0]), "r"(b[1]));
}

__device__ __forceinline__ void ldsm4(uint32_t* r, uint32_t addr) {
    asm volatile(
        "ldmatrix.sync.aligned.m8n8.x4.shared.b16 {%0,%1,%2,%3}, [%4];"
        : "=r"(r[0]), "=r"(r[1]), "=r"(r[2]), "=r"(r[3]) : "r"(addr));
}

__device__ __forceinline__ void ldsm4t(uint32_t* r, uint32_t addr) {
    asm volatile(
        "ldmatrix.sync.aligned.m8n8.x4.trans.shared.b16 {%0,%1,%2,%3}, [%4];"
        : "=r"(r[0]), "=r"(r[1]), "=r"(r[2]), "=r"(r[3]) : "r"(addr));
}

__device__ __forceinline__ uint32_t smem_u32(const void* p) {
    uint32_t a;
    asm("{ .reg .u64 t; cvta.to.shared.u64 t, %1; cvt.u32.u64 %0, t; }" : "=r"(a) : "l"(p));
    return a;
}

#define CP_ASYNC16(dst, src) \
    asm volatile("cp.async.cg.shared.global [%0], [%1], 16;" :: "r"(dst), "l"(src))
#define CP_COMMIT() asm volatile("cp.async.commit_group;" ::: "memory")
#define CP_WAIT0()  asm volatile("cp.async.wait_group 0;" ::: "memory")

// ---------------------------------------------------------------------------
// Prep 1: split all 4 fp32 weights into bf16 hi/lo (one launch).
// ---------------------------------------------------------------------------
__global__ void split_w4_kernel(const float* __restrict__ w0, const float* __restrict__ w1,
                                const float* __restrict__ w2, const float* __restrict__ w3) {
    int slot = blockIdx.y;
    const float* src = (slot == 0) ? w0 : (slot == 1) ? w1 : (slot == 2) ? w2 : w3;
    int i = blockIdx.x * 256 + threadIdx.x;
    float v = src[i];
    __nv_bfloat16 h = __float2bfloat16_rn(v);
    __nv_bfloat16 l = __float2bfloat16_rn(v - __bfloat162float(h));
    g_Wh[slot * 32768 + i] = h;
    g_Wl[slot * 32768 + i] = l;
}

// ---------------------------------------------------------------------------
// Prep 2: transpose-split x[b][c][n] -> xt[b][n][c] bf16 hi/lo.
// ---------------------------------------------------------------------------
__global__ void xpose_kernel(const float* __restrict__ x) {
    __shared__ float tsm[32][33];
    const int b = blockIdx.z, n0 = blockIdx.x * 32, c0 = blockIdx.y * 32;
    const int tx = threadIdx.x & 31, ty = threadIdx.x >> 5;
    const float* xb = x + (size_t)b * Cdim * Nn;
    #pragma unroll
    for (int i = 0; i < 4; i++)
        tsm[ty + 8 * i][tx] = xb[(size_t)(c0 + ty + 8 * i) * Nn + n0 + tx];
    __syncthreads();
    #pragma unroll
    for (int i = 0; i < 4; i++) {
        float v = tsm[tx][ty + 8 * i];
        __nv_bfloat16 h = __float2bfloat16_rn(v);
        __nv_bfloat16 l = __float2bfloat16_rn(v - __bfloat162float(h));
        size_t o = ((size_t)b * Nn + n0 + ty + 8 * i) * Cdim + c0 + tx;
        g_Xth[o] = h;
        g_Xtl[o] = l;
    }
}

// ---------------------------------------------------------------------------
// Kernel 1: QKV projection on tensor cores (unchanged from R14 pass).
// ---------------------------------------------------------------------------
#define P36 36
#define QKV_XH 0
#define QKV_XL (128 * P36)
#define QKV_WH (2 * 128 * P36)
#define QKV_WL (3 * 128 * P36)
#define QKV_SMEM (4 * 128 * P36 * 4)

__global__ void __launch_bounds__(256, 1) qkv_tc_kernel() {
    extern __shared__ uint32_t S[];
    const int b = blockIdx.z, slot = blockIdx.y, n0 = blockIdx.x * 128;
    const int tid = threadIdx.x;
    const int lane = tid & 31, w = tid >> 5;
    const int g = lane >> 2, t = lane & 3;
    const int row0 = w * 16 + g, row1 = row0 + 8;

    const uint32_t* Xhw = (const uint32_t*)g_Xth;
    const uint32_t* Xlw = (const uint32_t*)g_Xtl;
    const uint32_t* Whw = (const uint32_t*)(g_Wh + slot * 32768);
    const uint32_t* Wlw = (const uint32_t*)(g_Wl + slot * 32768);

    float acc[16][4];
    #pragma unroll
    for (int nb = 0; nb < 16; nb++)
        #pragma unroll
        for (int c = 0; c < 4; c++) acc[nb][c] = 0.f;

    for (int chunk = 0; chunk < 4; chunk++) {
        const int c0 = chunk * 64;
        __syncthreads();
        #pragma unroll
        for (int i = 0; i < 4; i++) {
            int f = tid + i * 256;
            int r = f >> 3, w4 = (f & 7) * 4;
            size_t xb = ((size_t)(b * Nn + n0 + r) * Cdim + c0) >> 1;
            *(uint4*)&S[QKV_XH + r * P36 + w4] = *(const uint4*)&Xhw[xb + w4];
            *(uint4*)&S[QKV_XL + r * P36 + w4] = *(const uint4*)&Xlw[xb + w4];
            int wb = r * 128 + (c0 >> 1);
            *(uint4*)&S[QKV_WH + r * P36 + w4] = *(const uint4*)&Whw[wb + w4];
            *(uint4*)&S[QKV_WL + r * P36 + w4] = *(const uint4*)&Wlw[wb + w4];
        }
        __syncthreads();

        #pragma unroll
        for (int kb = 0; kb < 4; kb++) {
            const int kw = kb * 8 + t;
            uint32_t ah[4], al[4];
            ah[0] = S[QKV_XH + row0 * P36 + kw];
            ah[1] = S[QKV_XH + row1 * P36 + kw];
            ah[2] = S[QKV_XH + row0 * P36 + kw + 4];
            ah[3] = S[QKV_XH + row1 * P36 + kw + 4];
            al[0] = S[QKV_XL + row0 * P36 + kw];
            al[1] = S[QKV_XL + row1 * P36 + kw];
            al[2] = S[QKV_XL + row0 * P36 + kw + 4];
            al[3] = S[QKV_XL + row1 * P36 + kw + 4];
            #pragma unroll
            for (int nb = 0; nb < 16; nb++) {
                const int rr = nb * 8 + g;
                uint32_t bh[2], bl[2];
                bh[0] = S[QKV_WH + rr * P36 + kw];
                bh[1] = S[QKV_WH + rr * P36 + kw + 4];
                bl[0] = S[QKV_WL + rr * P36 + kw];
                bl[1] = S[QKV_WL + rr * P36 + kw + 4];
                mma16(acc[nb], ah, bh);
                mma16(acc[nb], ah, bl);
                mma16(acc[nb], al, bh);
            }
        }
    }

    const size_t base0 = ((size_t)b * Nn + n0 + row0) * Ddim;
    const size_t base1 = ((size_t)b * Nn + n0 + row1) * Ddim;
    if (slot == 0) {
        #pragma unroll
        for (int nb = 0; nb < 16; nb++) {
            const int d = nb * 8 + t * 2;
            *(__half2*)&g_Q[base0 + d] = __floats2half2_rn(acc[nb][0], acc[nb][1]);
            *(__half2*)&g_Q[base1 + d] = __floats2half2_rn(acc[nb][2], acc[nb][3]);
        }
    } else if (slot == 2) {
        #pragma unroll
        for (int nb = 0; nb < 16; nb++) {
            const int d = nb * 8 + t * 2;
            *(__half2*)&g_V[base0 + d] = __floats2half2_rn(acc[nb][0], acc[nb][1]);
            *(__half2*)&g_V[base1 + d] = __floats2half2_rn(acc[nb][2], acc[nb][3]);
        }
    } else {
        #pragma unroll
        for (int nb = 0; nb < 16; nb++) {
            const int d = nb * 8 + t * 2;
            __half h00 = __float2half_rn(acc[nb][0]);
            __half h01 = __float2half_rn(acc[nb][1]);
            __half h10 = __float2half_rn(acc[nb][2]);
            __half h11 = __float2half_rn(acc[nb][3]);
            __half l00 = __float2half_rn(acc[nb][0] - __half2float(h00));
            __half l01 = __float2half_rn(acc[nb][1] - __half2float(h01));
            __half l10 = __float2half_rn(acc[nb][2] - __half2float(h10));
            __half l11 = __float2half_rn(acc[nb][3] - __half2float(h11));
            *(__half2*)&g_KhA[base0 + d] = __halves2half2(h00, h01);
            *(__half2*)&g_KhA[base1 + d] = __halves2half2(h10, h11);
            *(__half2*)&g_KlA[base0 + d] = __halves2half2(l00, l01);
            *(__half2*)&g_KlA[base1 + d] = __halves2half2(l10, l11);
        }
    }
}

// ---------------------------------------------------------------------------
// Kernel 2: flash attention. fp16 MMA path (R14 numerics, unchanged).
// NEW: cp.async double-buffered K/V staging (tile j+1 loads overlap tile j
// compute), deferred l-reduction (epilogue), rescale skipped when the warp's
// running max didn't change (exact skip: sc == 1.0).
// SMEM layout (words): Q[128*68] | 2 x {KH,KL,V}[64*68 each] | P[128*68]
// ---------------------------------------------------------------------------
#define QW 68
#define A_Q   0
#define A_KV  (128 * QW)
#define KVW   (64 * QW)          // one array
#define BUFW  (3 * KVW)          // one buffer (KH,KL,V)
#define A_PS  (A_KV + 2 * BUFW)
#define ATTN_WORDS (A_PS + 128 * QW)
#define ATTN_SMEM (ATTN_WORDS * 4)

__global__ void __launch_bounds__(256, 1) attn_kernel() {
    extern __shared__ float sm[];
    uint32_t* Qs = (uint32_t*)sm + A_Q;
    uint32_t* Pw = (uint32_t*)sm + A_PS;

    const uint32_t sb  = smem_u32(sm);
    const uint32_t bQS = sb + A_Q * 4;
    const uint32_t bKV = sb + A_KV * 4;
    const uint32_t bPS = sb + A_PS * 4;

    const int b  = blockIdx.y;
    const int q0 = blockIdx.x * 128;
    const uint32_t* Qg  = (const uint32_t*)(g_Q + ((size_t)b * Nn + q0) * Ddim);
    const uint32_t* Kgh = (const uint32_t*)(g_KhA + (size_t)b * Nn * Ddim);
    const uint32_t* Kgl = (const uint32_t*)(g_KlA + (size_t)b * Nn * Ddim);
    const uint32_t* Vg  = (const uint32_t*)(g_V + (size_t)b * Nn * Ddim);

    const int tid  = threadIdx.x;
    const int lane = tid & 31;
    const int w    = tid >> 5;
    const int g    = lane >> 2;
    const int t    = lane & 3;

    const uint32_t aOff = ((uint32_t)(w * 16 + (lane & 7) + ((lane >> 3) & 1) * 8) * QW
                          + (lane >> 4) * 4) * 4;
    const uint32_t bOff = ((uint32_t)((lane >> 4) * 8 + (lane & 7)) * QW
                          + ((lane >> 3) & 1) * 4) * 4;
    const uint32_t vOff = ((uint32_t)((lane & 7) + ((lane >> 3) & 1) * 8) * QW
                          + (lane >> 4) * 4) * 4;

    // staging coords for this thread (4 rows of 16B chunks per array)
    const int s_r  = tid >> 4;            // base row 0..15 (+16 per iter)
    const int s_cw = (tid & 15) * 4;      // word column

    // Q: 128 rows x 16 uint4 = 2048 uint4 -> 8 iterations of 256 threads
    #pragma unroll
    for (int i = 0; i < 8; i++) {
        int f = tid + i * 256;
        int r = f >> 4, cw = (f & 15) * 4;
        *(uint4*)&Qs[r * QW + cw] = *(const uint4*)&Qg[r * 64 + cw];
    }

    // prologue: stage tile 0 into buffer 0 via cp.async
    #pragma unroll
    for (int i = 0; i < 4; i++) {
        int r = s_r + i * 16;
        uint32_t so = (uint32_t)(r * QW + s_cw) * 4;
        CP_ASYNC16(bKV + so,            &Kgh[(size_t)r * 64 + s_cw]);
        CP_ASYNC16(bKV + KVW * 4 + so,  &Kgl[(size_t)r * 64 + s_cw]);
        CP_ASYNC16(bKV + 2 * KVW * 4 + so, &Vg[(size_t)r * 64 + s_cw]);
    }
    CP_COMMIT();

    float m0 = -1e30f, m1 = -1e30f, l0 = 0.f, l1 = 0.f;
    float o[16][4];
    #pragma unroll
    for (int nb = 0; nb < 16; nb++)
        #pragma unroll
        for (int c = 0; c < 4; c++) o[nb][c] = 0.f;

    const int row0 = w * 16 + g;
    const int row1 = row0 + 8;

    for (int j = 0; j < 64; j++) {
        const int buf = j & 1;
        const uint32_t kbH = bKV + (uint32_t)buf * BUFW * 4;
        const uint32_t kbL = kbH + KVW * 4;
        const uint32_t vbS = kbH + 2 * KVW * 4;

        CP_WAIT0();        // tile j's cp.async data landed (own thread)
        __syncthreads();   // everyone's landed; PV of j-1 done (other buffer free)

        // issue tile j+1 into the other buffer; overlaps this tile's compute
        if (j + 1 < 64) {
            const uint32_t dst = bKV + (uint32_t)(buf ^ 1) * BUFW * 4;
            const int jr = (j + 1) * 64;
            #pragma unroll
            for (int i = 0; i < 4; i++) {
                int r = s_r + i * 16;
                uint32_t so = (uint32_t)(r * QW + s_cw) * 4;
                CP_ASYNC16(dst + so,             &Kgh[(size_t)(jr + r) * 64 + s_cw]);
                CP_ASYNC16(dst + KVW * 4 + so,   &Kgl[(size_t)(jr + r) * 64 + s_cw]);
                CP_ASYNC16(dst + 2 * KVW * 4 + so, &Vg[(size_t)(jr + r) * 64 + s_cw]);
            }
            CP_COMMIT();
        }

        // ---- S = Q (Kh + Kl): fp16 2-split via ldmatrix ----
        float s[8][4];
        #pragma unroll
        for (int nb = 0; nb < 8; nb++)
            #pragma unroll
            for (int c = 0; c < 4; c++) s[nb][c] = 0.f;

        #pragma unroll
        for (int kb = 0; kb < 8; kb++) {
            const uint32_t kByte = kb * 32;
            uint32_t ah[4];
            ldsm4(ah, bQS + aOff + kByte);
            #pragma unroll
            for (int nbp = 0; nbp < 4; nbp++) {
                const uint32_t bo = bOff + (uint32_t)nbp * 16 * QW * 4 + kByte;
                uint32_t bh[4], bl[4];
                ldsm4(bh, kbH + bo);
                ldsm4(bl, kbL + bo);
                mma16h(s[2 * nbp],     ah, &bh[0]);
                mma16h(s[2 * nbp],     ah, &bl[0]);
                mma16h(s[2 * nbp + 1], ah, &bh[2]);
                mma16h(s[2 * nbp + 1], ah, &bl[2]);
            }
        }

        // ---- online softmax with running max ----
        float mx0 = -1e30f, mx1 = -1e30f;
        #pragma unroll
        for (int nb = 0; nb < 8; nb++) {
            mx0 = fmaxf(mx0, fmaxf(s[nb][0], s[nb][1]));
            mx1 = fmaxf(mx1, fmaxf(s[nb][2], s[nb][3]));
        }
        mx0 = fmaxf(mx0, __shfl_xor_sync(0xffffffffu, mx0, 1));
        mx0 = fmaxf(mx0, __shfl_xor_sync(0xffffffffu, mx0, 2));
        mx1 = fmaxf(mx1, __shfl_xor_sync(0xffffffffu, mx1, 1));
        mx1 = fmaxf(mx1, __shfl_xor_sync(0xffffffffu, mx1, 2));
        const float m0p = m0, m1p = m1;
        const float mn0 = fmaxf(m0, mx0), mn1 = fmaxf(m1, mx1);
        m0 = mn0; m1 = mn1;
        // rescale only if some lane's running max changed (exact: sc==1 otherwise)
        bool upd = (mn0 != m0p) || (mn1 != m1p);
        if (__any_sync(0xffffffffu, upd)) {
            float sc0 = __expf(m0p - mn0), sc1 = __expf(m1p - mn1);
            l0 *= sc0; l1 *= sc1;
            #pragma unroll
            for (int nb = 0; nb < 16; nb++) {
                o[nb][0] *= sc0; o[nb][1] *= sc0;
                o[nb][2] *= sc1; o[nb][3] *= sc1;
            }
        }
        // per-lane partial row sums (reduced once in epilogue)
        #pragma unroll
        for (int nb = 0; nb < 8; nb++) {
            float p0 = __expf(s[nb][0] - mn0);
            float p1 = __expf(s[nb][1] - mn0);
            float p2 = __expf(s[nb][2] - mn1);
            float p3 = __expf(s[nb][3] - mn1);
            l0 += p0 + p1;
            l1 += p2 + p3;
            __half2 hp0 = __floats2half2_rn(p0, p1);
            __half2 hp1 = __floats2half2_rn(p2, p3);
            *(__half2*)&Pw[row0 * QW + nb * 4 + t] = hp0;
            *(__half2*)&Pw[row1 * QW + nb * 4 + t] = hp1;
        }
        __syncwarp();  // P rows warp-private: order STS -> LDSM within warp

        // ---- O += P V : fp16 m16n8k16 ----
        #pragma unroll
        for (int kb = 0; kb < 4; kb++) {
            uint32_t pa[4];
            ldsm4(pa, bPS + aOff + kb * 32);
            #pragma unroll
            for (int nbp = 0; nbp < 8; nbp++) {
                uint32_t vb[4];
                ldsm4t(vb, vbS + vOff + (uint32_t)kb * 16 * QW * 4 + nbp * 32);
                mma16h(o[2 * nbp],     pa, &vb[0]);
                mma16h(o[2 * nbp + 1], pa, &vb[2]);
            }
        }
    }

    // ---- epilogue: reduce l across 4 lanes of the row, normalize, write ----
    l0 += __shfl_xor_sync(0xffffffffu, l0, 1);
    l0 += __shfl_xor_sync(0xffffffffu, l0, 2);
    l1 += __shfl_xor_sync(0xffffffffu, l1, 1);
    l1 += __shfl_xor_sync(0xffffffffu, l1, 2);
    float inv0 = 1.f / l0, inv1 = 1.f / l1;
    const size_t base0 = ((size_t)b * Nn + q0 + row0) * Ddim;
    const size_t base1 = ((size_t)b * Nn + q0 + row1) * Ddim;
    #pragma unroll
    for (int nb = 0; nb < 16; nb++) {
        const int d = nb * 8 + t * 2;
        float y00 = o[nb][0] * inv0, y01 = o[nb][1] * inv0;
        float y10 = o[nb][2] * inv1, y11 = o[nb][3] * inv1;
        __nv_bfloat162 h0, l0v, h1, l1v;
        h0.x = __float2bfloat16_rn(y00);
        h0.y = __float2bfloat16_rn(y01);
        l0v.x = __float2bfloat16_rn(y00 - __bfloat162float(h0.x));
        l0v.y = __float2bfloat16_rn(y01 - __bfloat162float(h0.y));
        h1.x = __float2bfloat16_rn(y10);
        h1.y = __float2bfloat16_rn(y11);
        l1v.x = __float2bfloat16_rn(y10 - __bfloat162float(h1.x));
        l1v.y = __float2bfloat16_rn(y11 - __bfloat162float(h1.y));
        *(__nv_bfloat162*)&g_Yh[base0 + d] = h0;
        *(__nv_bfloat162*)&g_Yl[base0 + d] = l0v;
        *(__nv_bfloat162*)&g_Yh[base1 + d] = h1;
        *(__nv_bfloat162*)&g_Yl[base1 + d] = l1v;
    }
}

// ---------------------------------------------------------------------------
// Kernel 3: out = x + w_out * y on tensor cores (unchanged from R14 pass).
// ---------------------------------------------------------------------------
#define OUT_AH 0
#define OUT_AL (128 * P36)
#define OUT_BH (2 * 128 * P36)
#define OUT_BL (2 * 128 * P36 + 64 * P36)
#define OUT_SMEM ((2 * 128 * P36 + 2 * 64 * P36) * 4)

__global__ void __launch_bounds__(256) out_tc_kernel(const float* __restrict__ x,
                                                     float* __restrict__ out) {
    extern __shared__ uint32_t S[];
    const int b = blockIdx.z, c0 = blockIdx.y * 128, n0 = blockIdx.x * 64;
    const int tid = threadIdx.x;
    const int lane = tid & 31, w = tid >> 5;
    const int g = lane >> 2, t = lane & 3;
    const int row0 = w * 16 + g, row1 = row0 + 8;

    const uint32_t* Ahw = (const uint32_t*)(g_Wh + 3 * 32768);
    const uint32_t* Alw = (const uint32_t*)(g_Wl + 3 * 32768);
    const uint32_t* Bhw = (const uint32_t*)g_Yh;
    const uint32_t* Blw = (const uint32_t*)g_Yl;

    float acc[8][4];
    #pragma unroll
    for (int nb = 0; nb < 8; nb++)
        #pragma unroll
        for (int c = 0; c < 4; c++) acc[nb][c] = 0.f;

    for (int chunk = 0; chunk < 2; chunk++) {
        const int dd0 = chunk * 64;
        __syncthreads();
        #pragma unroll
        for (int i = 0; i < 4; i++) {
            int f = tid + i * 256;
            int r = f >> 3, w4 = (f & 7) * 4;
            int ab = (c0 + r) * 64 + (dd0 >> 1);
            *(uint4*)&S[OUT_AH + r * P36 + w4] = *(const uint4*)&Ahw[ab + w4];
            *(uint4*)&S[OUT_AL + r * P36 + w4] = *(const uint4*)&Alw[ab + w4];
        }
        #pragma unroll
        for (int i = 0; i < 2; i++) {
            int f = tid + i * 256;
            int r = f >> 3, w4 = (f & 7) * 4;
            size_t bb = ((size_t)(b * Nn + n0 + r) * Ddim + dd0) >> 1;
            *(uint4*)&S[OUT_BH + r * P36 + w4] = *(const uint4*)&Bhw[bb + w4];
            *(uint4*)&S[OUT_BL + r * P36 + w4] = *(const uint4*)&Blw[bb + w4];
        }
        __syncthreads();

        #pragma unroll
        for (int kb = 0; kb < 4; kb++) {
            const int kw = kb * 8 + t;
            uint32_t ah[4], al[4];
            ah[0] = S[OUT_AH + row0 * P36 + kw];
            ah[1] = S[OUT_AH + row1 * P36 + kw];
            ah[2] = S[OUT_AH + row0 * P36 + kw + 4];
            ah[3] = S[OUT_AH + row1 * P36 + kw + 4];
            al[0] = S[OUT_AL + row0 * P36 + kw];
            al[1] = S[OUT_AL + row1 * P36 + kw];
            al[2] = S[OUT_AL + row0 * P36 + kw + 4];
            al[3] = S[OUT_AL + row1 * P36 + kw + 4];
            #pragma unroll
            for (int nb = 0; nb < 8; nb++) {
                const int rr = nb * 8 + g;
                uint32_t bh[2], bl[2];
                bh[0] = S[OUT_BH + rr * P36 + kw];
                bh[1] = S[OUT_BH + rr * P36 + kw + 4];
                bl[0] = S[OUT_BL + rr * P36 + kw];
                bl[1] = S[OUT_BL + rr * P36 + kw + 4];
                mma16(acc[nb], ah, bh);
                mma16(acc[nb], ah, bl);
                mma16(acc[nb], al, bh);
            }
        }
    }

    const int ch0 = c0 + row0, ch1 = c0 + row1;
    #pragma unroll
    for (int nb = 0; nb < 8; nb++) {
        const int pix = n0 + nb * 8 + t * 2;
        size_t i0 = (size_t)b * Cdim * Nn + (size_t)ch0 * Nn + pix;
        size_t i1 = (size_t)b * Cdim * Nn + (size_t)ch1 * Nn + pix;
        float2 x0 = *(const float2*)&x[i0];
        float2 x1 = *(const float2*)&x[i1];
        *(float2*)&out[i0] = make_float2(x0.x + acc[nb][0], x0.y + acc[nb][1]);
        *(float2*)&out[i1] = make_float2(x1.x + acc[nb][2], x1.y + acc[nb][3]);
    }
}

// ---------------------------------------------------------------------------
extern "C" void kernel_launch(void* const* d_in, const int* in_sizes, int n_in,
                              void* d_out, int out_size) {
    const float* x  = (const float*)d_in[0];
    const float* wt = (const float*)d_in[1];
    const float* wp = (const float*)d_in[2];
    const float* wg = (const float*)d_in[3];
    const float* wo = (const float*)d_in[4];
    float* out = (float*)d_out;

    cudaFuncSetAttribute(attn_kernel,
                         cudaFuncAttributeMaxDynamicSharedMemorySize, ATTN_SMEM);
    cudaFuncSetAttribute(qkv_tc_kernel,
                         cudaFuncAttributeMaxDynamicSharedMemorySize, QKV_SMEM);
    cudaFuncSetAttribute(out_tc_kernel,
                         cudaFuncAttributeMaxDynamicSharedMemorySize, OUT_SMEM);

    split_w4_kernel<<<dim3(128, 4), 256>>>(wt, wp, wg, wo);
    xpose_kernel<<<dim3(Nn / 32, Cdim / 32, Bsz), 256>>>(x);
    qkv_tc_kernel<<<dim3(Nn / 128, 3, Bsz), 256, QKV_SMEM>>>();
    attn_kernel<<<dim3(Nn / 128, Bsz), 256, ATTN_SMEM>>>();
    out_tc_kernel<<<dim3(Nn / 64, Cdim / 128, Bsz), 256, OUT_SMEM>>>(x, out);
}

// round 16
// speedup vs baseline: 1.6517x; 1.0838x over previous
#include <cuda_runtime.h>
#include <cuda_bf16.h>
#include <cuda_fp16.h>
#include <cstdint>
#include <math.h>

#define Bsz  4
#define Cdim 256
#define Ddim 128
#define Nn   4096

// Scratch (static __device__ — no allocations allowed)
__device__ __half g_Q[Bsz * Nn * Ddim];                // fp16 rounded Q
__device__ __half g_KhA[Bsz * Nn * Ddim];              // fp16 K hi
__device__ __half g_KlA[Bsz * Nn * Ddim];              // fp16 K lo
__device__ __half g_V[Bsz * Nn * Ddim];                // fp16 V
__device__ __nv_bfloat16 g_Yh[Bsz * Nn * Ddim];
__device__ __nv_bfloat16 g_Yl[Bsz * Nn * Ddim];
__device__ __nv_bfloat16 g_Xth[Bsz * Nn * Cdim];       // x^T split
__device__ __nv_bfloat16 g_Xtl[Bsz * Nn * Cdim];
__device__ __nv_bfloat16 g_Wh[4 * 32768];              // wt,wp,wg,w_out split
__device__ __nv_bfloat16 g_Wl[4 * 32768];

__device__ __forceinline__ void mma16(float* c, const uint32_t* a, const uint32_t* b) {
    asm volatile(
        "mma.sync.aligned.m16n8k16.row.col.f32.bf16.bf16.f32 "
        "{%0,%1,%2,%3},{%4,%5,%6,%7},{%8,%9},{%0,%1,%2,%3};"
        : "+f"(c[0]), "+f"(c[1]), "+f"(c[2]), "+f"(c[3])
        : "r"(a[0]), "r"(a[1]), "r"(a[2]), "r"(a[3]), "r"(b[0]), "r"(b[1]));
}

__device__ __forceinline__ void mma16h(float* c, const uint32_t* a, const uint32_t* b) {
    asm volatile(
        "mma.sync.aligned.m16n8k16.row.col.f32.f16.f16.f32 "
        "{%0,%1,%2,%3},{%4,%5,%6,%7},{%8,%9},{%0,%1,%2,%3};"
        : "+f"(c[0]), "+f"(c[1]), "+f"(c[2]), "+f"(c[3])
        : "r"(a[0]), "r"(a[1]), "r"(a[2]), "r"(a[3]), "r"(b[0]), "r"(b[1]));
}

__device__ __forceinline__ void ldsm4(uint32_t* r, uint32_t addr) {
    asm volatile(
        "ldmatrix.sync.aligned.m8n8.x4.shared.b16 {%0,%1,%2,%3}, [%4];"
        : "=r"(r[0]), "=r"(r[1]), "=r"(r[2]), "=r"(r[3]) : "r"(addr));
}

__device__ __forceinline__ void ldsm4t(uint32_t* r, uint32_t addr) {
    asm volatile(
        "ldmatrix.sync.aligned.m8n8.x4.trans.shared.b16 {%0,%1,%2,%3}, [%4];"
        : "=r"(r[0]), "=r"(r[1]), "=r"(r[2]), "=r"(r[3]) : "r"(addr));
}

__device__ __forceinline__ uint32_t smem_u32(const void* p) {
    uint32_t a;
    asm("{ .reg .u64 t; cvta.to.shared.u64 t, %1; cvt.u32.u64 %0, t; }" : "=r"(a) : "l"(p));
    return a;
}

#define CP_ASYNC16(dst, src) \
    asm volatile("cp.async.cg.shared.global [%0], [%1], 16;" :: "r"(dst), "l"(src))
#define CP_COMMIT() asm volatile("cp.async.commit_group;" ::: "memory")
#define CP_WAIT0()  asm volatile("cp.async.wait_group 0;" ::: "memory")

// ---------------------------------------------------------------------------
// Prep 1: split all 4 fp32 weights into bf16 hi/lo (one launch).
// ---------------------------------------------------------------------------
__global__ void split_w4_kernel(const float* __restrict__ w0, const float* __restrict__ w1,
                                const float* __restrict__ w2, const float* __restrict__ w3) {
    int slot = blockIdx.y;
    const float* src = (slot == 0) ? w0 : (slot == 1) ? w1 : (slot == 2) ? w2 : w3;
    int i = blockIdx.x * 256 + threadIdx.x;
    float v = src[i];
    __nv_bfloat16 h = __float2bfloat16_rn(v);
    __nv_bfloat16 l = __float2bfloat16_rn(v - __bfloat162float(h));
    g_Wh[slot * 32768 + i] = h;
    g_Wl[slot * 32768 + i] = l;
}

// ---------------------------------------------------------------------------
// Prep 2: transpose-split x[b][c][n] -> xt[b][n][c] bf16 hi/lo.
// ---------------------------------------------------------------------------
__global__ void xpose_kernel(const float* __restrict__ x) {
    __shared__ float tsm[32][33];
    const int b = blockIdx.z, n0 = blockIdx.x * 32, c0 = blockIdx.y * 32;
    const int tx = threadIdx.x & 31, ty = threadIdx.x >> 5;
    const float* xb = x + (size_t)b * Cdim * Nn;
    #pragma unroll
    for (int i = 0; i < 4; i++)
        tsm[ty + 8 * i][tx] = xb[(size_t)(c0 + ty + 8 * i) * Nn + n0 + tx];
    __syncthreads();
    #pragma unroll
    for (int i = 0; i < 4; i++) {
        float v = tsm[tx][ty + 8 * i];
        __nv_bfloat16 h = __float2bfloat16_rn(v);
        __nv_bfloat16 l = __float2bfloat16_rn(v - __bfloat162float(h));
        size_t o = ((size_t)b * Nn + n0 + ty + 8 * i) * Cdim + c0 + tx;
        g_Xth[o] = h;
        g_Xtl[o] = l;
    }
}

// ---------------------------------------------------------------------------
// Kernel 1: QKV projection on tensor cores (unchanged from R15 pass).
// ---------------------------------------------------------------------------
#define P36 36
#define QKV_XH 0
#define QKV_XL (128 * P36)
#define QKV_WH (2 * 128 * P36)
#define QKV_WL (3 * 128 * P36)
#define QKV_SMEM (4 * 128 * P36 * 4)

__global__ void __launch_bounds__(256, 1) qkv_tc_kernel() {
    extern __shared__ uint32_t S[];
    const int b = blockIdx.z, slot = blockIdx.y, n0 = blockIdx.x * 128;
    const int tid = threadIdx.x;
    const int lane = tid & 31, w = tid >> 5;
    const int g = lane >> 2, t = lane & 3;
    const int row0 = w * 16 + g, row1 = row0 + 8;

    const uint32_t* Xhw = (const uint32_t*)g_Xth;
    const uint32_t* Xlw = (const uint32_t*)g_Xtl;
    const uint32_t* Whw = (const uint32_t*)(g_Wh + slot * 32768);
    const uint32_t* Wlw = (const uint32_t*)(g_Wl + slot * 32768);

    float acc[16][4];
    #pragma unroll
    for (int nb = 0; nb < 16; nb++)
        #pragma unroll
        for (int c = 0; c < 4; c++) acc[nb][c] = 0.f;

    for (int chunk = 0; chunk < 4; chunk++) {
        const int c0 = chunk * 64;
        __syncthreads();
        #pragma unroll
        for (int i = 0; i < 4; i++) {
            int f = tid + i * 256;
            int r = f >> 3, w4 = (f & 7) * 4;
            size_t xb = ((size_t)(b * Nn + n0 + r) * Cdim + c0) >> 1;
            *(uint4*)&S[QKV_XH + r * P36 + w4] = *(const uint4*)&Xhw[xb + w4];
            *(uint4*)&S[QKV_XL + r * P36 + w4] = *(const uint4*)&Xlw[xb + w4];
            int wb = r * 128 + (c0 >> 1);
            *(uint4*)&S[QKV_WH + r * P36 + w4] = *(const uint4*)&Whw[wb + w4];
            *(uint4*)&S[QKV_WL + r * P36 + w4] = *(const uint4*)&Wlw[wb + w4];
        }
        __syncthreads();

        #pragma unroll
        for (int kb = 0; kb < 4; kb++) {
            const int kw = kb * 8 + t;
            uint32_t ah[4], al[4];
            ah[0] = S[QKV_XH + row0 * P36 + kw];
            ah[1] = S[QKV_XH + row1 * P36 + kw];
            ah[2] = S[QKV_XH + row0 * P36 + kw + 4];
            ah[3] = S[QKV_XH + row1 * P36 + kw + 4];
            al[0] = S[QKV_XL + row0 * P36 + kw];
            al[1] = S[QKV_XL + row1 * P36 + kw];
            al[2] = S[QKV_XL + row0 * P36 + kw + 4];
            al[3] = S[QKV_XL + row1 * P36 + kw + 4];
            #pragma unroll
            for (int nb = 0; nb < 16; nb++) {
                const int rr = nb * 8 + g;
                uint32_t bh[2], bl[2];
                bh[0] = S[QKV_WH + rr * P36 + kw];
                bh[1] = S[QKV_WH + rr * P36 + kw + 4];
                bl[0] = S[QKV_WL + rr * P36 + kw];
                bl[1] = S[QKV_WL + rr * P36 + kw + 4];
                mma16(acc[nb], ah, bh);
                mma16(acc[nb], ah, bl);
                mma16(acc[nb], al, bh);
            }
        }
    }

    const size_t base0 = ((size_t)b * Nn + n0 + row0) * Ddim;
    const size_t base1 = ((size_t)b * Nn + n0 + row1) * Ddim;
    if (slot == 0) {
        #pragma unroll
        for (int nb = 0; nb < 16; nb++) {
            const int d = nb * 8 + t * 2;
            *(__half2*)&g_Q[base0 + d] = __floats2half2_rn(acc[nb][0], acc[nb][1]);
            *(__half2*)&g_Q[base1 + d] = __floats2half2_rn(acc[nb][2], acc[nb][3]);
        }
    } else if (slot == 2) {
        #pragma unroll
        for (int nb = 0; nb < 16; nb++) {
            const int d = nb * 8 + t * 2;
            *(__half2*)&g_V[base0 + d] = __floats2half2_rn(acc[nb][0], acc[nb][1]);
            *(__half2*)&g_V[base1 + d] = __floats2half2_rn(acc[nb][2], acc[nb][3]);
        }
    } else {
        #pragma unroll
        for (int nb = 0; nb < 16; nb++) {
            const int d = nb * 8 + t * 2;
            __half h00 = __float2half_rn(acc[nb][0]);
            __half h01 = __float2half_rn(acc[nb][1]);
            __half h10 = __float2half_rn(acc[nb][2]);
            __half h11 = __float2half_rn(acc[nb][3]);
            __half l00 = __float2half_rn(acc[nb][0] - __half2float(h00));
            __half l01 = __float2half_rn(acc[nb][1] - __half2float(h01));
            __half l10 = __float2half_rn(acc[nb][2] - __half2float(h10));
            __half l11 = __float2half_rn(acc[nb][3] - __half2float(h11));
            *(__half2*)&g_KhA[base0 + d] = __halves2half2(h00, h01);
            *(__half2*)&g_KhA[base1 + d] = __halves2half2(h10, h11);
            *(__half2*)&g_KlA[base0 + d] = __halves2half2(l00, l01);
            *(__half2*)&g_KlA[base1 + d] = __halves2half2(l10, l11);
        }
    }
}

// ---------------------------------------------------------------------------
// Kernel 2: flash attention (R15 + register-resident P).
// The S C-frag element pairs ARE the PV A-frag half2 pairs:
//   MMA kb A-frag = { hp0(2kb), hp1(2kb), hp0(2kb+1), hp1(2kb+1) }.
// So P never goes through SMEM: no STS, no syncwarp, no LDSM for P.
// SMEM layout (words): Q[128*68] | 2 x {KH,KL,V}[64*68 each]  (139 KB)
// ---------------------------------------------------------------------------
#define QW 68
#define A_Q   0
#define A_KV  (128 * QW)
#define KVW   (64 * QW)          // one array
#define BUFW  (3 * KVW)          // one buffer (KH,KL,V)
#define ATTN_WORDS (A_KV + 2 * BUFW)
#define ATTN_SMEM (ATTN_WORDS * 4)

__global__ void __launch_bounds__(256, 1) attn_kernel() {
    extern __shared__ float sm[];
    uint32_t* Qs = (uint32_t*)sm + A_Q;

    const uint32_t sb  = smem_u32(sm);
    const uint32_t bQS = sb + A_Q * 4;
    const uint32_t bKV = sb + A_KV * 4;

    const int b  = blockIdx.y;
    const int q0 = blockIdx.x * 128;
    const uint32_t* Qg  = (const uint32_t*)(g_Q + ((size_t)b * Nn + q0) * Ddim);
    const uint32_t* Kgh = (const uint32_t*)(g_KhA + (size_t)b * Nn * Ddim);
    const uint32_t* Kgl = (const uint32_t*)(g_KlA + (size_t)b * Nn * Ddim);
    const uint32_t* Vg  = (const uint32_t*)(g_V + (size_t)b * Nn * Ddim);

    const int tid  = threadIdx.x;
    const int lane = tid & 31;
    const int w    = tid >> 5;
    const int g    = lane >> 2;
    const int t    = lane & 3;

    const uint32_t aOff = ((uint32_t)(w * 16 + (lane & 7) + ((lane >> 3) & 1) * 8) * QW
                          + (lane >> 4) * 4) * 4;
    const uint32_t bOff = ((uint32_t)((lane >> 4) * 8 + (lane & 7)) * QW
                          + ((lane >> 3) & 1) * 4) * 4;
    const uint32_t vOff = ((uint32_t)((lane & 7) + ((lane >> 3) & 1) * 8) * QW
                          + (lane >> 4) * 4) * 4;

    // staging coords for this thread (4 rows of 16B chunks per array)
    const int s_r  = tid >> 4;
    const int s_cw = (tid & 15) * 4;

    // Q: 128 rows x 16 uint4 = 2048 uint4 -> 8 iterations of 256 threads
    #pragma unroll
    for (int i = 0; i < 8; i++) {
        int f = tid + i * 256;
        int r = f >> 4, cw = (f & 15) * 4;
        *(uint4*)&Qs[r * QW + cw] = *(const uint4*)&Qg[r * 64 + cw];
    }

    // prologue: stage tile 0 into buffer 0 via cp.async
    #pragma unroll
    for (int i = 0; i < 4; i++) {
        int r = s_r + i * 16;
        uint32_t so = (uint32_t)(r * QW + s_cw) * 4;
        CP_ASYNC16(bKV + so,               &Kgh[(size_t)r * 64 + s_cw]);
        CP_ASYNC16(bKV + KVW * 4 + so,     &Kgl[(size_t)r * 64 + s_cw]);
        CP_ASYNC16(bKV + 2 * KVW * 4 + so, &Vg[(size_t)r * 64 + s_cw]);
    }
    CP_COMMIT();

    float m0 = -1e30f, m1 = -1e30f, l0 = 0.f, l1 = 0.f;
    float o[16][4];
    #pragma unroll
    for (int nb = 0; nb < 16; nb++)
        #pragma unroll
        for (int c = 0; c < 4; c++) o[nb][c] = 0.f;

    for (int j = 0; j < 64; j++) {
        const int buf = j & 1;
        const uint32_t kbH = bKV + (uint32_t)buf * BUFW * 4;
        const uint32_t kbL = kbH + KVW * 4;
        const uint32_t vbS = kbH + 2 * KVW * 4;

        CP_WAIT0();        // tile j's cp.async data landed (own thread)
        __syncthreads();   // everyone's landed; PV of j-1 done (other buffer free)

        // issue tile j+1 into the other buffer; overlaps this tile's compute
        if (j + 1 < 64) {
            const uint32_t dst = bKV + (uint32_t)(buf ^ 1) * BUFW * 4;
            const int jr = (j + 1) * 64;
            #pragma unroll
            for (int i = 0; i < 4; i++) {
                int r = s_r + i * 16;
                uint32_t so = (uint32_t)(r * QW + s_cw) * 4;
                CP_ASYNC16(dst + so,               &Kgh[(size_t)(jr + r) * 64 + s_cw]);
                CP_ASYNC16(dst + KVW * 4 + so,     &Kgl[(size_t)(jr + r) * 64 + s_cw]);
                CP_ASYNC16(dst + 2 * KVW * 4 + so, &Vg[(size_t)(jr + r) * 64 + s_cw]);
            }
            CP_COMMIT();
        }

        // ---- S = Q (Kh + Kl): fp16 2-split via ldmatrix ----
        float s[8][4];
        #pragma unroll
        for (int nb = 0; nb < 8; nb++)
            #pragma unroll
            for (int c = 0; c < 4; c++) s[nb][c] = 0.f;

        #pragma unroll
        for (int kb = 0; kb < 8; kb++) {
            const uint32_t kByte = kb * 32;
            uint32_t ah[4];
            ldsm4(ah, bQS + aOff + kByte);
            #pragma unroll
            for (int nbp = 0; nbp < 4; nbp++) {
                const uint32_t bo = bOff + (uint32_t)nbp * 16 * QW * 4 + kByte;
                uint32_t bh[4], bl[4];
                ldsm4(bh, kbH + bo);
                ldsm4(bl, kbL + bo);
                mma16h(s[2 * nbp],     ah, &bh[0]);
                mma16h(s[2 * nbp],     ah, &bl[0]);
                mma16h(s[2 * nbp + 1], ah, &bh[2]);
                mma16h(s[2 * nbp + 1], ah, &bl[2]);
            }
        }

        // ---- online softmax with running max ----
        float mx0 = -1e30f, mx1 = -1e30f;
        #pragma unroll
        for (int nb = 0; nb < 8; nb++) {
            mx0 = fmaxf(mx0, fmaxf(s[nb][0], s[nb][1]));
            mx1 = fmaxf(mx1, fmaxf(s[nb][2], s[nb][3]));
        }
        mx0 = fmaxf(mx0, __shfl_xor_sync(0xffffffffu, mx0, 1));
        mx0 = fmaxf(mx0, __shfl_xor_sync(0xffffffffu, mx0, 2));
        mx1 = fmaxf(mx1, __shfl_xor_sync(0xffffffffu, mx1, 1));
        mx1 = fmaxf(mx1, __shfl_xor_sync(0xffffffffu, mx1, 2));
        const float m0p = m0, m1p = m1;
        const float mn0 = fmaxf(m0, mx0), mn1 = fmaxf(m1, mx1);
        m0 = mn0; m1 = mn1;
        bool upd = (mn0 != m0p) || (mn1 != m1p);
        if (__any_sync(0xffffffffu, upd)) {
            float sc0 = __expf(m0p - mn0), sc1 = __expf(m1p - mn1);
            l0 *= sc0; l1 *= sc1;
            #pragma unroll
            for (int nb = 0; nb < 16; nb++) {
                o[nb][0] *= sc0; o[nb][1] *= sc0;
                o[nb][2] *= sc1; o[nb][3] *= sc1;
            }
        }
        // exp + pack P directly into PV A-frag registers (no SMEM round trip)
        uint32_t pfrag[16];
        #pragma unroll
        for (int nb = 0; nb < 8; nb++) {
            float p0 = __expf(s[nb][0] - mn0);
            float p1 = __expf(s[nb][1] - mn0);
            float p2 = __expf(s[nb][2] - mn1);
            float p3 = __expf(s[nb][3] - mn1);
            l0 += p0 + p1;
            l1 += p2 + p3;
            __half2 hp0 = __floats2half2_rn(p0, p1);
            __half2 hp1 = __floats2half2_rn(p2, p3);
            pfrag[2 * nb]     = *(uint32_t*)&hp0;
            pfrag[2 * nb + 1] = *(uint32_t*)&hp1;
        }

        // ---- O += P V : fp16 m16n8k16, A = pfrag (register-resident) ----
        #pragma unroll
        for (int kb = 0; kb < 4; kb++) {
            const uint32_t* pa = &pfrag[4 * kb];
            #pragma unroll
            for (int nbp = 0; nbp < 8; nbp++) {
                uint32_t vb[4];
                ldsm4t(vb, vbS + vOff + (uint32_t)kb * 16 * QW * 4 + nbp * 32);
                mma16h(o[2 * nbp],     pa, &vb[0]);
                mma16h(o[2 * nbp + 1], pa, &vb[2]);
            }
        }
    }

    // ---- epilogue: reduce l across 4 lanes of the row, normalize, write ----
    l0 += __shfl_xor_sync(0xffffffffu, l0, 1);
    l0 += __shfl_xor_sync(0xffffffffu, l0, 2);
    l1 += __shfl_xor_sync(0xffffffffu, l1, 1);
    l1 += __shfl_xor_sync(0xffffffffu, l1, 2);
    float inv0 = 1.f / l0, inv1 = 1.f / l1;
    const int row0 = w * 16 + g;
    const int row1 = row0 + 8;
    const size_t base0 = ((size_t)b * Nn + q0 + row0) * Ddim;
    const size_t base1 = ((size_t)b * Nn + q0 + row1) * Ddim;
    #pragma unroll
    for (int nb = 0; nb < 16; nb++) {
        const int d = nb * 8 + t * 2;
        float y00 = o[nb][0] * inv0, y01 = o[nb][1] * inv0;
        float y10 = o[nb][2] * inv1, y11 = o[nb][3] * inv1;
        __nv_bfloat162 h0, l0v, h1, l1v;
        h0.x = __float2bfloat16_rn(y00);
        h0.y = __float2bfloat16_rn(y01);
        l0v.x = __float2bfloat16_rn(y00 - __bfloat162float(h0.x));
        l0v.y = __float2bfloat16_rn(y01 - __bfloat162float(h0.y));
        h1.x = __float2bfloat16_rn(y10);
        h1.y = __float2bfloat16_rn(y11);
        l1v.x = __float2bfloat16_rn(y10 - __bfloat162float(h1.x));
        l1v.y = __float2bfloat16_rn(y11 - __bfloat162float(h1.y));
        *(__nv_bfloat162*)&g_Yh[base0 + d] = h0;
        *(__nv_bfloat162*)&g_Yl[base0 + d] = l0v;
        *(__nv_bfloat162*)&g_Yh[base1 + d] = h1;
        *(__nv_bfloat162*)&g_Yl[base1 + d] = l1v;
    }
}

// ---------------------------------------------------------------------------
// Kernel 3: out = x + w_out * y on tensor cores (unchanged from R15 pass).
// ---------------------------------------------------------------------------
#define OUT_AH 0
#define OUT_AL (128 * P36)
#define OUT_BH (2 * 128 * P36)
#define OUT_BL (2 * 128 * P36 + 64 * P36)
#define OUT_SMEM ((2 * 128 * P36 + 2 * 64 * P36) * 4)

__global__ void __launch_bounds__(256) out_tc_kernel(const float* __restrict__ x,
                                                     float* __restrict__ out) {
    extern __shared__ uint32_t S[];
    const int b = blockIdx.z, c0 = blockIdx.y * 128, n0 = blockIdx.x * 64;
    const int tid = threadIdx.x;
    const int lane = tid & 31, w = tid >> 5;
    const int g = lane >> 2, t = lane & 3;
    const int row0 = w * 16 + g, row1 = row0 + 8;

    const uint32_t* Ahw = (const uint32_t*)(g_Wh + 3 * 32768);
    const uint32_t* Alw = (const uint32_t*)(g_Wl + 3 * 32768);
    const uint32_t* Bhw = (const uint32_t*)g_Yh;
    const uint32_t* Blw = (const uint32_t*)g_Yl;

    float acc[8][4];
    #pragma unroll
    for (int nb = 0; nb < 8; nb++)
        #pragma unroll
        for (int c = 0; c < 4; c++) acc[nb][c] = 0.f;

    for (int chunk = 0; chunk < 2; chunk++) {
        const int dd0 = chunk * 64;
        __syncthreads();
        #pragma unroll
        for (int i = 0; i < 4; i++) {
            int f = tid + i * 256;
            int r = f >> 3, w4 = (f & 7) * 4;
            int ab = (c0 + r) * 64 + (dd0 >> 1);
            *(uint4*)&S[OUT_AH + r * P36 + w4] = *(const uint4*)&Ahw[ab + w4];
            *(uint4*)&S[OUT_AL + r * P36 + w4] = *(const uint4*)&Alw[ab + w4];
        }
        #pragma unroll
        for (int i = 0; i < 2; i++) {
            int f = tid + i * 256;
            int r = f >> 3, w4 = (f & 7) * 4;
            size_t bb = ((size_t)(b * Nn + n0 + r) * Ddim + dd0) >> 1;
            *(uint4*)&S[OUT_BH + r * P36 + w4] = *(const uint4*)&Bhw[bb + w4];
            *(uint4*)&S[OUT_BL + r * P36 + w4] = *(const uint4*)&Blw[bb + w4];
        }
        __syncthreads();

        #pragma unroll
        for (int kb = 0; kb < 4; kb++) {
            const int kw = kb * 8 + t;
            uint32_t ah[4], al[4];
            ah[0] = S[OUT_AH + row0 * P36 + kw];
            ah[1] = S[OUT_AH + row1 * P36 + kw];
            ah[2] = S[OUT_AH + row0 * P36 + kw + 4];
            ah[3] = S[OUT_AH + row1 * P36 + kw + 4];
            al[0] = S[OUT_AL + row0 * P36 + kw];
            al[1] = S[OUT_AL + row1 * P36 + kw];
            al[2] = S[OUT_AL + row0 * P36 + kw + 4];
            al[3] = S[OUT_AL + row1 * P36 + kw + 4];
            #pragma unroll
            for (int nb = 0; nb < 8; nb++) {
                const int rr = nb * 8 + g;
                uint32_t bh[2], bl[2];
                bh[0] = S[OUT_BH + rr * P36 + kw];
                bh[1] = S[OUT_BH + rr * P36 + kw + 4];
                bl[0] = S[OUT_BL + rr * P36 + kw];
                bl[1] = S[OUT_BL + rr * P36 + kw + 4];
                mma16(acc[nb], ah, bh);
                mma16(acc[nb], ah, bl);
                mma16(acc[nb], al, bh);
            }
        }
    }

    const int ch0 = c0 + row0, ch1 = c0 + row1;
    #pragma unroll
    for (int nb = 0; nb < 8; nb++) {
        const int pix = n0 + nb * 8 + t * 2;
        size_t i0 = (size_t)b * Cdim * Nn + (size_t)ch0 * Nn + pix;
        size_t i1 = (size_t)b * Cdim * Nn + (size_t)ch1 * Nn + pix;
        float2 x0 = *(const float2*)&x[i0];
        float2 x1 = *(const float2*)&x[i1];
        *(float2*)&out[i0] = make_float2(x0.x + acc[nb][0], x0.y + acc[nb][1]);
        *(float2*)&out[i1] = make_float2(x1.x + acc[nb][2], x1.y + acc[nb][3]);
    }
}

// ---------------------------------------------------------------------------
extern "C" void kernel_launch(void* const* d_in, const int* in_sizes, int n_in,
                              void* d_out, int out_size) {
    const float* x  = (const float*)d_in[0];
    const float* wt = (const float*)d_in[1];
    const float* wp = (const float*)d_in[2];
    const float* wg = (const float*)d_in[3];
    const float* wo = (const float*)d_in[4];
    float* out = (float*)d_out;

    cudaFuncSetAttribute(attn_kernel,
                         cudaFuncAttributeMaxDynamicSharedMemorySize, ATTN_SMEM);
    cudaFuncSetAttribute(qkv_tc_kernel,
                         cudaFuncAttributeMaxDynamicSharedMemorySize, QKV_SMEM);
    cudaFuncSetAttribute(out_tc_kernel,
                         cudaFuncAttributeMaxDynamicSharedMemorySize, OUT_SMEM);

    split_w4_kernel<<<dim3(128, 4), 256>>>(wt, wp, wg, wo);
    xpose_kernel<<<dim3(Nn / 32, Cdim / 32, Bsz), 256>>>(x);
    qkv_tc_kernel<<<dim3(Nn / 128, 3, Bsz), 256, QKV_SMEM>>>();
    attn_kernel<<<dim3(Nn / 128, Bsz), 256, ATTN_SMEM>>>();
    out_tc_kernel<<<dim3(Nn / 64, Cdim / 128, Bsz), 256, OUT_SMEM>>>(x, out);
}

// round 17
// speedup vs baseline: 1.7087x; 1.0345x over previous
#include <cuda_runtime.h>
#include <cuda_bf16.h>
#include <cuda_fp16.h>
#include <cstdint>
#include <math.h>

#define Bsz  4
#define Cdim 256
#define Ddim 128
#define Nn   4096

// Scratch (static __device__ — no allocations allowed)
__device__ __half g_Q[Bsz * Nn * Ddim];                // fp16 rounded Q
__device__ __half g_KhA[Bsz * Nn * Ddim];              // fp16 K hi
__device__ __half g_KlA[Bsz * Nn * Ddim];              // fp16 K lo
__device__ __half g_V[Bsz * Nn * Ddim];                // fp16 V
__device__ __nv_bfloat16 g_Yh[Bsz * Nn * Ddim];
__device__ __nv_bfloat16 g_Yl[Bsz * Nn * Ddim];
__device__ __nv_bfloat16 g_Xth[Bsz * Nn * Cdim];       // x^T split
__device__ __nv_bfloat16 g_Xtl[Bsz * Nn * Cdim];
__device__ __nv_bfloat16 g_Wh[4 * 32768];              // wt,wp,wg,w_out split
__device__ __nv_bfloat16 g_Wl[4 * 32768];

__device__ __forceinline__ void mma16(float* c, const uint32_t* a, const uint32_t* b) {
    asm volatile(
        "mma.sync.aligned.m16n8k16.row.col.f32.bf16.bf16.f32 "
        "{%0,%1,%2,%3},{%4,%5,%6,%7},{%8,%9},{%0,%1,%2,%3};"
        : "+f"(c[0]), "+f"(c[1]), "+f"(c[2]), "+f"(c[3])
        : "r"(a[0]), "r"(a[1]), "r"(a[2]), "r"(a[3]), "r"(b[0]), "r"(b[1]));
}

__device__ __forceinline__ void mma16h(float* c, const uint32_t* a, const uint32_t* b) {
    asm volatile(
        "mma.sync.aligned.m16n8k16.row.col.f32.f16.f16.f32 "
        "{%0,%1,%2,%3},{%4,%5,%6,%7},{%8,%9},{%0,%1,%2,%3};"
        : "+f"(c[0]), "+f"(c[1]), "+f"(c[2]), "+f"(c[3])
        : "r"(a[0]), "r"(a[1]), "r"(a[2]), "r"(a[3]), "r"(b[0]), "r"(b[1]));
}

__device__ __forceinline__ void ldsm4(uint32_t* r, uint32_t addr) {
    asm volatile(
        "ldmatrix.sync.aligned.m8n8.x4.shared.b16 {%0,%1,%2,%3}, [%4];"
        : "=r"(r[0]), "=r"(r[1]), "=r"(r[2]), "=r"(r[3]) : "r"(addr));
}

__device__ __forceinline__ void ldsm4t(uint32_t* r, uint32_t addr) {
    asm volatile(
        "ldmatrix.sync.aligned.m8n8.x4.trans.shared.b16 {%0,%1,%2,%3}, [%4];"
        : "=r"(r[0]), "=r"(r[1]), "=r"(r[2]), "=r"(r[3]) : "r"(addr));
}

__device__ __forceinline__ uint32_t smem_u32(const void* p) {
    uint32_t a;
    asm("{ .reg .u64 t; cvta.to.shared.u64 t, %1; cvt.u32.u64 %0, t; }" : "=r"(a) : "l"(p));
    return a;
}

#define CP_ASYNC16(dst, src) \
    asm volatile("cp.async.cg.shared.global [%0], [%1], 16;" :: "r"(dst), "l"(src))
#define CP_COMMIT() asm volatile("cp.async.commit_group;" ::: "memory")
#define CP_WAIT0()  asm volatile("cp.async.wait_group 0;" ::: "memory")

// ---------------------------------------------------------------------------
// Prep 1: split all 4 fp32 weights into bf16 hi/lo (one launch).
// ---------------------------------------------------------------------------
__global__ void split_w4_kernel(const float* __restrict__ w0, const float* __restrict__ w1,
                                const float* __restrict__ w2, const float* __restrict__ w3) {
    int slot = blockIdx.y;
    const float* src = (slot == 0) ? w0 : (slot == 1) ? w1 : (slot == 2) ? w2 : w3;
    int i = blockIdx.x * 256 + threadIdx.x;
    float v = src[i];
    __nv_bfloat16 h = __float2bfloat16_rn(v);
    __nv_bfloat16 l = __float2bfloat16_rn(v - __bfloat162float(h));
    g_Wh[slot * 32768 + i] = h;
    g_Wl[slot * 32768 + i] = l;
}

// ---------------------------------------------------------------------------
// Prep 2: transpose-split x[b][c][n] -> xt[b][n][c] bf16 hi/lo.
// ---------------------------------------------------------------------------
__global__ void xpose_kernel(const float* __restrict__ x) {
    __shared__ float tsm[32][33];
    const int b = blockIdx.z, n0 = blockIdx.x * 32, c0 = blockIdx.y * 32;
    const int tx = threadIdx.x & 31, ty = threadIdx.x >> 5;
    const float* xb = x + (size_t)b * Cdim * Nn;
    #pragma unroll
    for (int i = 0; i < 4; i++)
        tsm[ty + 8 * i][tx] = xb[(size_t)(c0 + ty + 8 * i) * Nn + n0 + tx];
    __syncthreads();
    #pragma unroll
    for (int i = 0; i < 4; i++) {
        float v = tsm[tx][ty + 8 * i];
        __nv_bfloat16 h = __float2bfloat16_rn(v);
        __nv_bfloat16 l = __float2bfloat16_rn(v - __bfloat162float(h));
        size_t o = ((size_t)b * Nn + n0 + ty + 8 * i) * Cdim + c0 + tx;
        g_Xth[o] = h;
        g_Xtl[o] = l;
    }
}

// ---------------------------------------------------------------------------
// Kernel 1: QKV projection on tensor cores. Operand fetches now via ldmatrix
// (identical fragment elements and MMA order as the R16 scalar version).
// ---------------------------------------------------------------------------
#define P36 36
#define QKV_XH 0
#define QKV_XL (128 * P36)
#define QKV_WH (2 * 128 * P36)
#define QKV_WL (3 * 128 * P36)
#define QKV_SMEM (4 * 128 * P36 * 4)

__global__ void __launch_bounds__(256, 1) qkv_tc_kernel() {
    extern __shared__ uint32_t S[];
    const int b = blockIdx.z, slot = blockIdx.y, n0 = blockIdx.x * 128;
    const int tid = threadIdx.x;
    const int lane = tid & 31, w = tid >> 5;
    const int g = lane >> 2, t = lane & 3;
    const int row0 = w * 16 + g, row1 = row0 + 8;

    const uint32_t sb  = smem_u32(S);
    const uint32_t bXH = sb + QKV_XH * 4;
    const uint32_t bXL = sb + QKV_XL * 4;
    const uint32_t bWH = sb + QKV_WH * 4;
    const uint32_t bWL = sb + QKV_WL * 4;
    const uint32_t aOffq = ((uint32_t)(w * 16 + (lane & 7) + ((lane >> 3) & 1) * 8) * P36
                           + (lane >> 4) * 4) * 4;
    const uint32_t bOffq = ((uint32_t)((lane >> 4) * 8 + (lane & 7)) * P36
                           + ((lane >> 3) & 1) * 4) * 4;

    const uint32_t* Xhw = (const uint32_t*)g_Xth;
    const uint32_t* Xlw = (const uint32_t*)g_Xtl;
    const uint32_t* Whw = (const uint32_t*)(g_Wh + slot * 32768);
    const uint32_t* Wlw = (const uint32_t*)(g_Wl + slot * 32768);

    float acc[16][4];
    #pragma unroll
    for (int nb = 0; nb < 16; nb++)
        #pragma unroll
        for (int c = 0; c < 4; c++) acc[nb][c] = 0.f;

    for (int chunk = 0; chunk < 4; chunk++) {
        const int c0 = chunk * 64;
        __syncthreads();
        #pragma unroll
        for (int i = 0; i < 4; i++) {
            int f = tid + i * 256;
            int r = f >> 3, w4 = (f & 7) * 4;
            size_t xb = ((size_t)(b * Nn + n0 + r) * Cdim + c0) >> 1;
            *(uint4*)&S[QKV_XH + r * P36 + w4] = *(const uint4*)&Xhw[xb + w4];
            *(uint4*)&S[QKV_XL + r * P36 + w4] = *(const uint4*)&Xlw[xb + w4];
            int wb = r * 128 + (c0 >> 1);
            *(uint4*)&S[QKV_WH + r * P36 + w4] = *(const uint4*)&Whw[wb + w4];
            *(uint4*)&S[QKV_WL + r * P36 + w4] = *(const uint4*)&Wlw[wb + w4];
        }
        __syncthreads();

        #pragma unroll
        for (int kb = 0; kb < 4; kb++) {
            const uint32_t kByte = kb * 32;
            uint32_t ah[4], al[4];
            ldsm4(ah, bXH + aOffq + kByte);
            ldsm4(al, bXL + aOffq + kByte);
            #pragma unroll
            for (int nbp = 0; nbp < 8; nbp++) {
                const uint32_t bo = bOffq + (uint32_t)nbp * 16 * P36 * 4 + kByte;
                uint32_t bh[4], bl[4];
                ldsm4(bh, bWH + bo);
                ldsm4(bl, bWL + bo);
                mma16(acc[2 * nbp],     ah, &bh[0]);
                mma16(acc[2 * nbp],     ah, &bl[0]);
                mma16(acc[2 * nbp],     al, &bh[0]);
                mma16(acc[2 * nbp + 1], ah, &bh[2]);
                mma16(acc[2 * nbp + 1], ah, &bl[2]);
                mma16(acc[2 * nbp + 1], al, &bh[2]);
            }
        }
    }

    const size_t base0 = ((size_t)b * Nn + n0 + row0) * Ddim;
    const size_t base1 = ((size_t)b * Nn + n0 + row1) * Ddim;
    if (slot == 0) {
        #pragma unroll
        for (int nb = 0; nb < 16; nb++) {
            const int d = nb * 8 + t * 2;
            *(__half2*)&g_Q[base0 + d] = __floats2half2_rn(acc[nb][0], acc[nb][1]);
            *(__half2*)&g_Q[base1 + d] = __floats2half2_rn(acc[nb][2], acc[nb][3]);
        }
    } else if (slot == 2) {
        #pragma unroll
        for (int nb = 0; nb < 16; nb++) {
            const int d = nb * 8 + t * 2;
            *(__half2*)&g_V[base0 + d] = __floats2half2_rn(acc[nb][0], acc[nb][1]);
            *(__half2*)&g_V[base1 + d] = __floats2half2_rn(acc[nb][2], acc[nb][3]);
        }
    } else {
        #pragma unroll
        for (int nb = 0; nb < 16; nb++) {
            const int d = nb * 8 + t * 2;
            __half h00 = __float2half_rn(acc[nb][0]);
            __half h01 = __float2half_rn(acc[nb][1]);
            __half h10 = __float2half_rn(acc[nb][2]);
            __half h11 = __float2half_rn(acc[nb][3]);
            __half l00 = __float2half_rn(acc[nb][0] - __half2float(h00));
            __half l01 = __float2half_rn(acc[nb][1] - __half2float(h01));
            __half l10 = __float2half_rn(acc[nb][2] - __half2float(h10));
            __half l11 = __float2half_rn(acc[nb][3] - __half2float(h11));
            *(__half2*)&g_KhA[base0 + d] = __halves2half2(h00, h01);
            *(__half2*)&g_KhA[base1 + d] = __halves2half2(h10, h11);
            *(__half2*)&g_KlA[base0 + d] = __halves2half2(l00, l01);
            *(__half2*)&g_KlA[base1 + d] = __halves2half2(l10, l11);
        }
    }
}

// ---------------------------------------------------------------------------
// Kernel 2: flash attention (R16 + Q fragments hoisted into registers).
// ---------------------------------------------------------------------------
#define QW 68
#define A_Q   0
#define A_KV  (128 * QW)
#define KVW   (64 * QW)
#define BUFW  (3 * KVW)
#define ATTN_WORDS (A_KV + 2 * BUFW)
#define ATTN_SMEM (ATTN_WORDS * 4)

__global__ void __launch_bounds__(256, 1) attn_kernel() {
    extern __shared__ float sm[];
    uint32_t* Qs = (uint32_t*)sm + A_Q;

    const uint32_t sb  = smem_u32(sm);
    const uint32_t bQS = sb + A_Q * 4;
    const uint32_t bKV = sb + A_KV * 4;

    const int b  = blockIdx.y;
    const int q0 = blockIdx.x * 128;
    const uint32_t* Qg  = (const uint32_t*)(g_Q + ((size_t)b * Nn + q0) * Ddim);
    const uint32_t* Kgh = (const uint32_t*)(g_KhA + (size_t)b * Nn * Ddim);
    const uint32_t* Kgl = (const uint32_t*)(g_KlA + (size_t)b * Nn * Ddim);
    const uint32_t* Vg  = (const uint32_t*)(g_V + (size_t)b * Nn * Ddim);

    const int tid  = threadIdx.x;
    const int lane = tid & 31;
    const int w    = tid >> 5;
    const int g    = lane >> 2;
    const int t    = lane & 3;

    const uint32_t aOff = ((uint32_t)(w * 16 + (lane & 7) + ((lane >> 3) & 1) * 8) * QW
                          + (lane >> 4) * 4) * 4;
    const uint32_t bOff = ((uint32_t)((lane >> 4) * 8 + (lane & 7)) * QW
                          + ((lane >> 3) & 1) * 4) * 4;
    const uint32_t vOff = ((uint32_t)((lane & 7) + ((lane >> 3) & 1) * 8) * QW
                          + (lane >> 4) * 4) * 4;

    const int s_r  = tid >> 4;
    const int s_cw = (tid & 15) * 4;

    // Q: 128 rows x 16 uint4 = 2048 uint4 -> 8 iterations of 256 threads
    #pragma unroll
    for (int i = 0; i < 8; i++) {
        int f = tid + i * 256;
        int r = f >> 4, cw = (f & 15) * 4;
        *(uint4*)&Qs[r * QW + cw] = *(const uint4*)&Qg[r * 64 + cw];
    }

    // prologue: stage tile 0 into buffer 0 via cp.async
    #pragma unroll
    for (int i = 0; i < 4; i++) {
        int r = s_r + i * 16;
        uint32_t so = (uint32_t)(r * QW + s_cw) * 4;
        CP_ASYNC16(bKV + so,               &Kgh[(size_t)r * 64 + s_cw]);
        CP_ASYNC16(bKV + KVW * 4 + so,     &Kgl[(size_t)r * 64 + s_cw]);
        CP_ASYNC16(bKV + 2 * KVW * 4 + so, &Vg[(size_t)r * 64 + s_cw]);
    }
    CP_COMMIT();

    // hoist Q fragments into registers (tile-invariant)
    __syncthreads();
    uint32_t qfrag[8][4];
    #pragma unroll
    for (int kb = 0; kb < 8; kb++)
        ldsm4(qfrag[kb], bQS + aOff + (uint32_t)kb * 32);

    float m0 = -1e30f, m1 = -1e30f, l0 = 0.f, l1 = 0.f;
    float o[16][4];
    #pragma unroll
    for (int nb = 0; nb < 16; nb++)
        #pragma unroll
        for (int c = 0; c < 4; c++) o[nb][c] = 0.f;

    for (int j = 0; j < 64; j++) {
        const int buf = j & 1;
        const uint32_t kbH = bKV + (uint32_t)buf * BUFW * 4;
        const uint32_t kbL = kbH + KVW * 4;
        const uint32_t vbS = kbH + 2 * KVW * 4;

        CP_WAIT0();
        __syncthreads();

        if (j + 1 < 64) {
            const uint32_t dst = bKV + (uint32_t)(buf ^ 1) * BUFW * 4;
            const int jr = (j + 1) * 64;
            #pragma unroll
            for (int i = 0; i < 4; i++) {
                int r = s_r + i * 16;
                uint32_t so = (uint32_t)(r * QW + s_cw) * 4;
                CP_ASYNC16(dst + so,               &Kgh[(size_t)(jr + r) * 64 + s_cw]);
                CP_ASYNC16(dst + KVW * 4 + so,     &Kgl[(size_t)(jr + r) * 64 + s_cw]);
                CP_ASYNC16(dst + 2 * KVW * 4 + so, &Vg[(size_t)(jr + r) * 64 + s_cw]);
            }
            CP_COMMIT();
        }

        // ---- S = Q (Kh + Kl): fp16 2-split; Q from registers ----
        float s[8][4];
        #pragma unroll
        for (int nb = 0; nb < 8; nb++)
            #pragma unroll
            for (int c = 0; c < 4; c++) s[nb][c] = 0.f;

        #pragma unroll
        for (int kb = 0; kb < 8; kb++) {
            const uint32_t kByte = kb * 32;
            const uint32_t* ah = qfrag[kb];
            #pragma unroll
            for (int nbp = 0; nbp < 4; nbp++) {
                const uint32_t bo = bOff + (uint32_t)nbp * 16 * QW * 4 + kByte;
                uint32_t bh[4], bl[4];
                ldsm4(bh, kbH + bo);
                ldsm4(bl, kbL + bo);
                mma16h(s[2 * nbp],     ah, &bh[0]);
                mma16h(s[2 * nbp],     ah, &bl[0]);
                mma16h(s[2 * nbp + 1], ah, &bh[2]);
                mma16h(s[2 * nbp + 1], ah, &bl[2]);
            }
        }

        // ---- online softmax with running max ----
        float mx0 = -1e30f, mx1 = -1e30f;
        #pragma unroll
        for (int nb = 0; nb < 8; nb++) {
            mx0 = fmaxf(mx0, fmaxf(s[nb][0], s[nb][1]));
            mx1 = fmaxf(mx1, fmaxf(s[nb][2], s[nb][3]));
        }
        mx0 = fmaxf(mx0, __shfl_xor_sync(0xffffffffu, mx0, 1));
        mx0 = fmaxf(mx0, __shfl_xor_sync(0xffffffffu, mx0, 2));
        mx1 = fmaxf(mx1, __shfl_xor_sync(0xffffffffu, mx1, 1));
        mx1 = fmaxf(mx1, __shfl_xor_sync(0xffffffffu, mx1, 2));
        const float m0p = m0, m1p = m1;
        const float mn0 = fmaxf(m0, mx0), mn1 = fmaxf(m1, mx1);
        m0 = mn0; m1 = mn1;
        bool upd = (mn0 != m0p) || (mn1 != m1p);
        if (__any_sync(0xffffffffu, upd)) {
            float sc0 = __expf(m0p - mn0), sc1 = __expf(m1p - mn1);
            l0 *= sc0; l1 *= sc1;
            #pragma unroll
            for (int nb = 0; nb < 16; nb++) {
                o[nb][0] *= sc0; o[nb][1] *= sc0;
                o[nb][2] *= sc1; o[nb][3] *= sc1;
            }
        }
        uint32_t pfrag[16];
        #pragma unroll
        for (int nb = 0; nb < 8; nb++) {
            float p0 = __expf(s[nb][0] - mn0);
            float p1 = __expf(s[nb][1] - mn0);
            float p2 = __expf(s[nb][2] - mn1);
            float p3 = __expf(s[nb][3] - mn1);
            l0 += p0 + p1;
            l1 += p2 + p3;
            __half2 hp0 = __floats2half2_rn(p0, p1);
            __half2 hp1 = __floats2half2_rn(p2, p3);
            pfrag[2 * nb]     = *(uint32_t*)&hp0;
            pfrag[2 * nb + 1] = *(uint32_t*)&hp1;
        }

        // ---- O += P V : fp16 m16n8k16, A = pfrag (register-resident) ----
        #pragma unroll
        for (int kb = 0; kb < 4; kb++) {
            const uint32_t* pa = &pfrag[4 * kb];
            #pragma unroll
            for (int nbp = 0; nbp < 8; nbp++) {
                uint32_t vb[4];
                ldsm4t(vb, vbS + vOff + (uint32_t)kb * 16 * QW * 4 + nbp * 32);
                mma16h(o[2 * nbp],     pa, &vb[0]);
                mma16h(o[2 * nbp + 1], pa, &vb[2]);
            }
        }
    }

    // ---- epilogue ----
    l0 += __shfl_xor_sync(0xffffffffu, l0, 1);
    l0 += __shfl_xor_sync(0xffffffffu, l0, 2);
    l1 += __shfl_xor_sync(0xffffffffu, l1, 1);
    l1 += __shfl_xor_sync(0xffffffffu, l1, 2);
    float inv0 = 1.f / l0, inv1 = 1.f / l1;
    const int row0 = w * 16 + g;
    const int row1 = row0 + 8;
    const size_t base0 = ((size_t)b * Nn + q0 + row0) * Ddim;
    const size_t base1 = ((size_t)b * Nn + q0 + row1) * Ddim;
    #pragma unroll
    for (int nb = 0; nb < 16; nb++) {
        const int d = nb * 8 + t * 2;
        float y00 = o[nb][0] * inv0, y01 = o[nb][1] * inv0;
        float y10 = o[nb][2] * inv1, y11 = o[nb][3] * inv1;
        __nv_bfloat162 h0, l0v, h1, l1v;
        h0.x = __float2bfloat16_rn(y00);
        h0.y = __float2bfloat16_rn(y01);
        l0v.x = __float2bfloat16_rn(y00 - __bfloat162float(h0.x));
        l0v.y = __float2bfloat16_rn(y01 - __bfloat162float(h0.y));
        h1.x = __float2bfloat16_rn(y10);
        h1.y = __float2bfloat16_rn(y11);
        l1v.x = __float2bfloat16_rn(y10 - __bfloat162float(h1.x));
        l1v.y = __float2bfloat16_rn(y11 - __bfloat162float(h1.y));
        *(__nv_bfloat162*)&g_Yh[base0 + d] = h0;
        *(__nv_bfloat162*)&g_Yl[base0 + d] = l0v;
        *(__nv_bfloat162*)&g_Yh[base1 + d] = h1;
        *(__nv_bfloat162*)&g_Yl[base1 + d] = l1v;
    }
}

// ---------------------------------------------------------------------------
// Kernel 3: out = x + w_out * y on tensor cores, LDSM operand path
// (identical fragments and MMA order as the R16 scalar version).
// ---------------------------------------------------------------------------
#define OUT_AH 0
#define OUT_AL (128 * P36)
#define OUT_BH (2 * 128 * P36)
#define OUT_BL (2 * 128 * P36 + 64 * P36)
#define OUT_SMEM ((2 * 128 * P36 + 2 * 64 * P36) * 4)

__global__ void __launch_bounds__(256) out_tc_kernel(const float* __restrict__ x,
                                                     float* __restrict__ out) {
    extern __shared__ uint32_t S[];
    const int b = blockIdx.z, c0 = blockIdx.y * 128, n0 = blockIdx.x * 64;
    const int tid = threadIdx.x;
    const int lane = tid & 31, w = tid >> 5;
    const int g = lane >> 2, t = lane & 3;
    const int row0 = w * 16 + g, row1 = row0 + 8;

    const uint32_t sb  = smem_u32(S);
    const uint32_t bAH = sb + OUT_AH * 4;
    const uint32_t bAL = sb + OUT_AL * 4;
    const uint32_t bBH = sb + OUT_BH * 4;
    const uint32_t bBL = sb + OUT_BL * 4;
    const uint32_t aOffo = ((uint32_t)(w * 16 + (lane & 7) + ((lane >> 3) & 1) * 8) * P36
                           + (lane >> 4) * 4) * 4;
    const uint32_t bOffo = ((uint32_t)((lane >> 4) * 8 + (lane & 7)) * P36
                           + ((lane >> 3) & 1) * 4) * 4;

    const uint32_t* Ahw = (const uint32_t*)(g_Wh + 3 * 32768);
    const uint32_t* Alw = (const uint32_t*)(g_Wl + 3 * 32768);
    const uint32_t* Bhw = (const uint32_t*)g_Yh;
    const uint32_t* Blw = (const uint32_t*)g_Yl;

    float acc[8][4];
    #pragma unroll
    for (int nb = 0; nb < 8; nb++)
        #pragma unroll
        for (int c = 0; c < 4; c++) acc[nb][c] = 0.f;

    for (int chunk = 0; chunk < 2; chunk++) {
        const int dd0 = chunk * 64;
        __syncthreads();
        #pragma unroll
        for (int i = 0; i < 4; i++) {
            int f = tid + i * 256;
            int r = f >> 3, w4 = (f & 7) * 4;
            int ab = (c0 + r) * 64 + (dd0 >> 1);
            *(uint4*)&S[OUT_AH + r * P36 + w4] = *(const uint4*)&Ahw[ab + w4];
            *(uint4*)&S[OUT_AL + r * P36 + w4] = *(const uint4*)&Alw[ab + w4];
        }
        #pragma unroll
        for (int i = 0; i < 2; i++) {
            int f = tid + i * 256;
            int r = f >> 3, w4 = (f & 7) * 4;
            size_t bb = ((size_t)(b * Nn + n0 + r) * Ddim + dd0) >> 1;
            *(uint4*)&S[OUT_BH + r * P36 + w4] = *(const uint4*)&Bhw[bb + w4];
            *(uint4*)&S[OUT_BL + r * P36 + w4] = *(const uint4*)&Blw[bb + w4];
        }
        __syncthreads();

        #pragma unroll
        for (int kb = 0; kb < 4; kb++) {
            const uint32_t kByte = kb * 32;
            uint32_t ah[4], al[4];
            ldsm4(ah, bAH + aOffo + kByte);
            ldsm4(al, bAL + aOffo + kByte);
            #pragma unroll
            for (int nbp = 0; nbp < 4; nbp++) {
                const uint32_t bo = bOffo + (uint32_t)nbp * 16 * P36 * 4 + kByte;
                uint32_t bh[4], bl[4];
                ldsm4(bh, bBH + bo);
                ldsm4(bl, bBL + bo);
                mma16(acc[2 * nbp],     ah, &bh[0]);
                mma16(acc[2 * nbp],     ah, &bl[0]);
                mma16(acc[2 * nbp],     al, &bh[0]);
                mma16(acc[2 * nbp + 1], ah, &bh[2]);
                mma16(acc[2 * nbp + 1], ah, &bl[2]);
                mma16(acc[2 * nbp + 1], al, &bh[2]);
            }
        }
    }

    const int ch0 = c0 + row0, ch1 = c0 + row1;
    #pragma unroll
    for (int nb = 0; nb < 8; nb++) {
        const int pix = n0 + nb * 8 + t * 2;
        size_t i0 = (size_t)b * Cdim * Nn + (size_t)ch0 * Nn + pix;
        size_t i1 = (size_t)b * Cdim * Nn + (size_t)ch1 * Nn + pix;
        float2 x0 = *(const float2*)&x[i0];
        float2 x1 = *(const float2*)&x[i1];
        *(float2*)&out[i0] = make_float2(x0.x + acc[nb][0], x0.y + acc[nb][1]);
        *(float2*)&out[i1] = make_float2(x1.x + acc[nb][2], x1.y + acc[nb][3]);
    }
}

// ---------------------------------------------------------------------------
extern "C" void kernel_launch(void* const* d_in, const int* in_sizes, int n_in,
                              void* d_out, int out_size) {
    const float* x  = (const float*)d_in[0];
    const float* wt = (const float*)d_in[1];
    const float* wp = (const float*)d_in[2];
    const float* wg = (const float*)d_in[3];
    const float* wo = (const float*)d_in[4];
    float* out = (float*)d_out;

    cudaFuncSetAttribute(attn_kernel,
                         cudaFuncAttributeMaxDynamicSharedMemorySize, ATTN_SMEM);
    cudaFuncSetAttribute(qkv_tc_kernel,
                         cudaFuncAttributeMaxDynamicSharedMemorySize, QKV_SMEM);
    cudaFuncSetAttribute(out_tc_kernel,
                         cudaFuncAttributeMaxDynamicSharedMemorySize, OUT_SMEM);

    split_w4_kernel<<<dim3(128, 4), 256>>>(wt, wp, wg, wo);
    xpose_kernel<<<dim3(Nn / 32, Cdim / 32, Bsz), 256>>>(x);
    qkv_tc_kernel<<<dim3(Nn / 128, 3, Bsz), 256, QKV_SMEM>>>();
    attn_kernel<<<dim3(Nn / 128, Bsz), 256, ATTN_SMEM>>>();
    out_tc_kernel<<<dim3(Nn / 64, Cdim / 128, Bsz), 256, OUT_SMEM>>>(x, out);
}